// round 1
// baseline (speedup 1.0000x reference)
#include <cuda_runtime.h>
#include <math.h>
#include <float.h>

// Problem constants
#define B_    4
#define S_    512
#define E_    1024
#define H_    16
#define D_    64
#define HD_   1024
#define XL_   512
#define J_    1024      // XL + S
#define TOPK_ 8
#define ST_   4096      // S * TOPK
#define MROWS 2048      // B * S

// Static scratch (no allocations allowed)
__device__ float g_q[B_*S_*HD_];
__device__ float g_k[B_*S_*HD_];
__device__ float g_v[B_*S_*HD_];
__device__ float g_kcat[B_*J_*HD_];
__device__ float g_vcat[B_*J_*HD_];
__device__ float g_fused[B_*S_*HD_];
__device__ float g_sm[(size_t)B_*H_*S_*J_];    // 128 MB main scores
__device__ float g_se[(size_t)B_*H_*S_*ST_];   // 512 MB ext scores

// ---------------------------------------------------------------------------
// Block reductions (256 threads)
// ---------------------------------------------------------------------------
__device__ __forceinline__ float blockMax256(float v) {
    __shared__ float sh[8];
    #pragma unroll
    for (int o = 16; o > 0; o >>= 1) v = fmaxf(v, __shfl_xor_sync(0xffffffffu, v, o));
    if ((threadIdx.x & 31) == 0) sh[threadIdx.x >> 5] = v;
    __syncthreads();
    if (threadIdx.x < 32) {
        float w = (threadIdx.x < 8) ? sh[threadIdx.x] : -FLT_MAX;
        #pragma unroll
        for (int o = 4; o > 0; o >>= 1) w = fmaxf(w, __shfl_xor_sync(0xffffffffu, w, o));
        if (threadIdx.x == 0) sh[0] = w;
    }
    __syncthreads();
    float r = sh[0];
    __syncthreads();
    return r;
}

__device__ __forceinline__ float blockSum256(float v) {
    __shared__ float sh[8];
    #pragma unroll
    for (int o = 16; o > 0; o >>= 1) v += __shfl_xor_sync(0xffffffffu, v, o);
    if ((threadIdx.x & 31) == 0) sh[threadIdx.x >> 5] = v;
    __syncthreads();
    if (threadIdx.x < 32) {
        float w = (threadIdx.x < 8) ? sh[threadIdx.x] : 0.0f;
        #pragma unroll
        for (int o = 4; o > 0; o >>= 1) w += __shfl_xor_sync(0xffffffffu, w, o);
        if (threadIdx.x == 0) sh[0] = w;
    }
    __syncthreads();
    float r = sh[0];
    __syncthreads();
    return r;
}

// ---------------------------------------------------------------------------
// Generic C = A @ W^T + bias  (A: MxK ld=K, W: NxK ld=K, C: MxN)
// Tile 64x64x16, 256 threads, 4x4 per thread
// ---------------------------------------------------------------------------
__global__ void gemm_bias_nt(const float* __restrict__ A, const float* __restrict__ W,
                             const float* __restrict__ bias, float* __restrict__ C,
                             int M, int N, int K) {
    __shared__ float As[16][64];
    __shared__ float Bs[16][64];
    const int tid = threadIdx.x;
    const int bm = blockIdx.y * 64, bn = blockIdx.x * 64;
    const int lm = tid >> 2;
    const int lk = (tid & 3) * 4;
    const float* Ap = A + (long)(bm + lm) * K + lk;
    const float* Wp = W + (long)(bn + lm) * K + lk;
    const int tm = (tid >> 4) << 2, tn = (tid & 15) << 2;
    float acc[4][4] = {};
    for (int k0 = 0; k0 < K; k0 += 16) {
        float4 a = *(const float4*)(Ap + k0);
        float4 b = *(const float4*)(Wp + k0);
        As[lk+0][lm] = a.x; As[lk+1][lm] = a.y; As[lk+2][lm] = a.z; As[lk+3][lm] = a.w;
        Bs[lk+0][lm] = b.x; Bs[lk+1][lm] = b.y; Bs[lk+2][lm] = b.z; Bs[lk+3][lm] = b.w;
        __syncthreads();
        #pragma unroll
        for (int k = 0; k < 16; k++) {
            float4 av = *(const float4*)&As[k][tm];
            float4 bv = *(const float4*)&Bs[k][tn];
            float ar[4] = {av.x, av.y, av.z, av.w};
            float br[4] = {bv.x, bv.y, bv.z, bv.w};
            #pragma unroll
            for (int i = 0; i < 4; i++)
                #pragma unroll
                for (int j = 0; j < 4; j++)
                    acc[i][j] = fmaf(ar[i], br[j], acc[i][j]);
        }
        __syncthreads();
    }
    #pragma unroll
    for (int i = 0; i < 4; i++)
        #pragma unroll
        for (int j = 0; j < 4; j++)
            C[(long)(bm + tm + i) * N + bn + tn + j] = acc[i][j] + bias[bn + tn + j];
}

// ---------------------------------------------------------------------------
// L2-normalize rows of length HD_ (B*S rows). x <- x / max(||x||, 1e-12)
// ---------------------------------------------------------------------------
__global__ void l2norm_rows(float* __restrict__ x) {
    const long base = (long)blockIdx.x * HD_;
    float ss = 0.0f;
    for (int c = threadIdx.x; c < HD_; c += 256) { float v = x[base + c]; ss += v * v; }
    ss = blockSum256(ss);
    const float inv = 1.0f / fmaxf(sqrtf(ss), 1e-12f);
    for (int c = threadIdx.x; c < HD_; c += 256) x[base + c] *= inv;
}

// ---------------------------------------------------------------------------
// Build kcat/vcat (xl_memory ++ new k/v) and write current_kv output
// ---------------------------------------------------------------------------
__global__ void concat_copy(const float* __restrict__ xl, float* __restrict__ out_kv) {
    const long idx = (long)blockIdx.x * 256 + threadIdx.x;   // over B*J*HD
    const int c = (int)(idx % HD_);
    const long r = idx / HD_;
    const int j = (int)(r % J_);
    const int b = (int)(r / J_);
    float kc, vc;
    if (j < XL_) {
        const long base = (((long)b * XL_ + j) * 2) * HD_;
        kc = xl[base + c];
        vc = xl[base + HD_ + c];
    } else {
        const int s = j - XL_;
        const long base = ((long)b * S_ + s) * HD_ + c;
        kc = g_k[base];
        vc = g_v[base];
        const long ob = (((long)b * S_ + s) * 2) * HD_;
        out_kv[ob + c] = kc;
        out_kv[ob + HD_ + c] = vc;
    }
    g_kcat[idx] = kc;
    g_vcat[idx] = vc;
}

// ---------------------------------------------------------------------------
// Scores: per (b,h): S x N = q(SxD) @ k(NxD)^T ;  k rows at stride kld
// ---------------------------------------------------------------------------
__global__ void score_gemm(const float* __restrict__ qb, const float* __restrict__ kb,
                           float* __restrict__ sb, int N, int kld, long kbatch) {
    __shared__ float As[16][64];
    __shared__ float Bs[16][64];
    const int z = blockIdx.z;
    const int b = z >> 4, h = z & 15;
    const int tid = threadIdx.x;
    const int bm = blockIdx.y * 64, bn = blockIdx.x * 64;
    const int lm = tid >> 2;
    const int lk = (tid & 3) * 4;
    const float* Ap = qb + ((long)b * S_ + bm + lm) * HD_ + h * D_ + lk;
    const float* Kp = kb + (long)b * kbatch + (long)(bn + lm) * kld + h * D_ + lk;
    const int tm = (tid >> 4) << 2, tn = (tid & 15) << 2;
    float acc[4][4] = {};
    #pragma unroll
    for (int k0 = 0; k0 < D_; k0 += 16) {
        float4 a = *(const float4*)(Ap + k0);
        float4 b4 = *(const float4*)(Kp + k0);
        As[lk+0][lm] = a.x; As[lk+1][lm] = a.y; As[lk+2][lm] = a.z; As[lk+3][lm] = a.w;
        Bs[lk+0][lm] = b4.x; Bs[lk+1][lm] = b4.y; Bs[lk+2][lm] = b4.z; Bs[lk+3][lm] = b4.w;
        __syncthreads();
        #pragma unroll
        for (int k = 0; k < 16; k++) {
            float4 av = *(const float4*)&As[k][tm];
            float4 bv = *(const float4*)&Bs[k][tn];
            float ar[4] = {av.x, av.y, av.z, av.w};
            float br[4] = {bv.x, bv.y, bv.z, bv.w};
            #pragma unroll
            for (int i = 0; i < 4; i++)
                #pragma unroll
                for (int j = 0; j < 4; j++)
                    acc[i][j] = fmaf(ar[i], br[j], acc[i][j]);
        }
        __syncthreads();
    }
    float* Cr = sb + (long)z * S_ * N;
    #pragma unroll
    for (int i = 0; i < 4; i++)
        #pragma unroll
        for (int j = 0; j < 4; j++)
            Cr[(long)(bm + tm + i) * N + bn + tn + j] = acc[i][j];
}

// ---------------------------------------------------------------------------
// Main softmax: val = (s + rel_pos) * scale, causal mask j <= XL + i
// ---------------------------------------------------------------------------
__global__ void softmax_main(float* __restrict__ s, const float* __restrict__ rel) {
    const long row = blockIdx.x;                   // (b*H+h)*S + i
    const int i = (int)(row & (S_ - 1));
    const int h = (int)((row >> 9) & 15);
    float* sr = s + row * J_;
    const float* rr = rel + ((long)h * S_ + i) * J_;
    const int jmax = XL_ + i;
    const float scale = 0.125f;                    // D^-0.5
    float vals[4];
    float m = -FLT_MAX;
    #pragma unroll
    for (int u = 0; u < 4; u++) {
        const int j = threadIdx.x + u * 256;
        const bool ok = (j <= jmax);
        float v = ok ? (sr[j] + rr[j]) * scale : -FLT_MAX;
        vals[u] = ok ? v : -FLT_MAX;
        m = fmaxf(m, vals[u]);
    }
    m = blockMax256(m);
    float ssum = 0.0f;
    #pragma unroll
    for (int u = 0; u < 4; u++) {
        float e = (vals[u] == -FLT_MAX) ? 0.0f : __expf(vals[u] - m);
        vals[u] = e;
        ssum += e;
    }
    ssum = blockSum256(ssum);
    const float inv = 1.0f / ssum;
    #pragma unroll
    for (int u = 0; u < 4; u++) {
        const int j = threadIdx.x + u * 256;
        sr[j] = vals[u] * inv;
    }
}

// ---------------------------------------------------------------------------
// Ext softmax: rows of length ST_ (4096), val = s * scale, no mask
// ---------------------------------------------------------------------------
__global__ void softmax_ext(float* __restrict__ s) {
    const long row = blockIdx.x;
    float* sr = s + row * (long)ST_;
    float vals[16];
    float m = -FLT_MAX;
    #pragma unroll
    for (int u = 0; u < 16; u++) {
        const int j = threadIdx.x + u * 256;
        float v = sr[j] * 0.125f;
        vals[u] = v;
        m = fmaxf(m, v);
    }
    m = blockMax256(m);
    float ssum = 0.0f;
    #pragma unroll
    for (int u = 0; u < 16; u++) {
        float e = __expf(vals[u] - m);
        vals[u] = e;
        ssum += e;
    }
    ssum = blockSum256(ssum);
    const float inv = 1.0f / ssum;
    #pragma unroll
    for (int u = 0; u < 16; u++) {
        const int j = threadIdx.x + u * 256;
        sr[j] = vals[u] * inv;
    }
}

// ---------------------------------------------------------------------------
// AV: per (b,h): C(SxD) = P(SxKd) @ V(KdxD). V rows at stride vld, byte plane
// offset voff. Epilogue: fused = g*C (main) or fused += (1-g)*C (ext)
// ---------------------------------------------------------------------------
__global__ void av_gemm(const float* __restrict__ pb, const float* __restrict__ vb,
                        float* __restrict__ fused, const float* __restrict__ gate,
                        int Kd, int vld, long vbatch, int voff, int isExt) {
    __shared__ float As[16][64];
    __shared__ float Bs[16][64];
    const int z = blockIdx.z;
    const int b = z >> 4, h = z & 15;
    const int tid = threadIdx.x;
    const int bm = blockIdx.y * 64;
    const int lm = tid >> 2;
    const int lk = (tid & 3) * 4;
    const int vk = tid >> 4;             // 0..15
    const int vn = (tid & 15) * 4;       // 0..60
    const float* Pp = pb + ((long)z * S_ + bm + lm) * Kd + lk;
    const float* Vp = vb + (long)b * vbatch + voff + h * D_ + vn;
    const int tm = (tid >> 4) << 2, tn = (tid & 15) << 2;
    float acc[4][4] = {};
    for (int k0 = 0; k0 < Kd; k0 += 16) {
        float4 a = *(const float4*)(Pp + k0);
        float4 v4 = *(const float4*)(Vp + (long)(k0 + vk) * vld);
        As[lk+0][lm] = a.x; As[lk+1][lm] = a.y; As[lk+2][lm] = a.z; As[lk+3][lm] = a.w;
        *(float4*)&Bs[vk][vn] = v4;
        __syncthreads();
        #pragma unroll
        for (int k = 0; k < 16; k++) {
            float4 av = *(const float4*)&As[k][tm];
            float4 bv = *(const float4*)&Bs[k][tn];
            float ar[4] = {av.x, av.y, av.z, av.w};
            float br[4] = {bv.x, bv.y, bv.z, bv.w};
            #pragma unroll
            for (int i = 0; i < 4; i++)
                #pragma unroll
                for (int j = 0; j < 4; j++)
                    acc[i][j] = fmaf(ar[i], br[j], acc[i][j]);
        }
        __syncthreads();
    }
    const float gv = gate[h];
    const float g = 1.0f / (1.0f + __expf(-gv));
    const float f = isExt ? (1.0f - g) : g;
    #pragma unroll
    for (int i = 0; i < 4; i++) {
        #pragma unroll
        for (int j = 0; j < 4; j++) {
            const long idx = ((long)b * S_ + bm + tm + i) * HD_ + h * D_ + tn + j;
            if (isExt) fused[idx] += f * acc[i][j];
            else       fused[idx] = f * acc[i][j];
        }
    }
}

// ---------------------------------------------------------------------------
extern "C" void kernel_launch(void* const* d_in, const int* in_sizes, int n_in,
                              void* d_out, int out_size) {
    const float* input = (const float*)d_in[0];
    const float* rel   = (const float*)d_in[1];
    const float* xl    = (const float*)d_in[2];
    const float* kve   = (const float*)d_in[3];
    const float* Wq = (const float*)d_in[4];  const float* bq = (const float*)d_in[5];
    const float* Wk = (const float*)d_in[6];  const float* bk = (const float*)d_in[7];
    const float* Wv = (const float*)d_in[8];  const float* bv = (const float*)d_in[9];
    const float* Wo = (const float*)d_in[10]; const float* bo = (const float*)d_in[11];
    const float* gate = (const float*)d_in[12];

    float* out = (float*)d_out;                    // (B,S,E)
    float* out_kv = out + (long)B_ * S_ * E_;      // (B,S,2,HD)

    float *q, *k, *v, *kcat, *vcat, *fused, *sm, *se;
    cudaGetSymbolAddress((void**)&q, g_q);
    cudaGetSymbolAddress((void**)&k, g_k);
    cudaGetSymbolAddress((void**)&v, g_v);
    cudaGetSymbolAddress((void**)&kcat, g_kcat);
    cudaGetSymbolAddress((void**)&vcat, g_vcat);
    cudaGetSymbolAddress((void**)&fused, g_fused);
    cudaGetSymbolAddress((void**)&sm, g_sm);
    cudaGetSymbolAddress((void**)&se, g_se);

    const dim3 t(256);
    const dim3 gproj(E_ / 64, MROWS / 64);

    // Projections
    gemm_bias_nt<<<gproj, t>>>(input, Wq, bq, q, MROWS, HD_, E_);
    gemm_bias_nt<<<gproj, t>>>(input, Wk, bk, k, MROWS, HD_, E_);
    gemm_bias_nt<<<gproj, t>>>(input, Wv, bv, v, MROWS, HD_, E_);
    // L2 norm over full HD (before head split, per reference)
    l2norm_rows<<<MROWS, t>>>(q);
    l2norm_rows<<<MROWS, t>>>(k);
    // Concat xl memory with new k/v; also emit current_kv output
    concat_copy<<<(B_ * J_ * HD_) / 256, t>>>(xl, out_kv);

    // Main attention
    score_gemm<<<dim3(J_ / 64, S_ / 64, B_ * H_), t>>>(q, kcat, sm, J_, HD_, (long)J_ * HD_);
    softmax_main<<<B_ * H_ * S_, t>>>(sm, rel);
    av_gemm<<<dim3(1, S_ / 64, B_ * H_), t>>>(sm, vcat, fused, gate, J_, HD_, (long)J_ * HD_, 0, 0);

    // External kNN attention (keys at plane 0, values at plane 1, row stride 2*HD)
    score_gemm<<<dim3(ST_ / 64, S_ / 64, B_ * H_), t>>>(q, kve, se, ST_, 2 * HD_,
                                                        (long)S_ * TOPK_ * 2 * HD_);
    softmax_ext<<<B_ * H_ * S_, t>>>(se);
    av_gemm<<<dim3(1, S_ / 64, B_ * H_), t>>>(se, kve, fused, gate, ST_, 2 * HD_,
                                              (long)S_ * TOPK_ * 2 * HD_, HD_, 1);

    // Output projection
    gemm_bias_nt<<<gproj, t>>>(fused, Wo, bo, out, MROWS, E_, HD_);
}

// round 2
// speedup vs baseline: 1.9552x; 1.9552x over previous
#include <cuda_runtime.h>
#include <math.h>
#include <float.h>

// Problem constants
#define B_    4
#define S_    512
#define E_    1024
#define H_    16
#define D_    64
#define HD_   1024
#define XL_   512
#define J_    1024      // XL + S
#define TOPK_ 8
#define ST_   4096      // S * TOPK
#define MROWS 2048      // B * S

// Static scratch (no allocations allowed)
__device__ float g_q[B_*S_*HD_];
__device__ float g_k[B_*S_*HD_];
__device__ float g_v[B_*S_*HD_];
__device__ float g_fused[B_*S_*HD_];

// ---------------------------------------------------------------------------
// tf32 helpers
// ---------------------------------------------------------------------------
__device__ __forceinline__ unsigned tf32u(float x) {
    unsigned u;
    asm("cvt.rna.tf32.f32 %0, %1;" : "=r"(u) : "f"(x));
    return u;
}
__device__ __forceinline__ float tf32f(float x) { return __uint_as_float(tf32u(x)); }

__device__ __forceinline__ void mma8(float* c, const unsigned* a, unsigned b0, unsigned b1) {
    asm volatile(
        "mma.sync.aligned.m16n8k8.row.col.f32.tf32.tf32.f32 "
        "{%0,%1,%2,%3},{%4,%5,%6,%7},{%8,%9},{%0,%1,%2,%3};"
        : "+f"(c[0]), "+f"(c[1]), "+f"(c[2]), "+f"(c[3])
        : "r"(a[0]), "r"(a[1]), "r"(a[2]), "r"(a[3]), "r"(b0), "r"(b1));
}

// ---------------------------------------------------------------------------
// Block reduction (256 threads)
// ---------------------------------------------------------------------------
__device__ __forceinline__ float blockSum256(float v) {
    __shared__ float sh[8];
    #pragma unroll
    for (int o = 16; o > 0; o >>= 1) v += __shfl_xor_sync(0xffffffffu, v, o);
    if ((threadIdx.x & 31) == 0) sh[threadIdx.x >> 5] = v;
    __syncthreads();
    if (threadIdx.x < 32) {
        float w = (threadIdx.x < 8) ? sh[threadIdx.x] : 0.0f;
        #pragma unroll
        for (int o = 4; o > 0; o >>= 1) w += __shfl_xor_sync(0xffffffffu, w, o);
        if (threadIdx.x == 0) sh[0] = w;
    }
    __syncthreads();
    float r = sh[0];
    __syncthreads();
    return r;
}

// ---------------------------------------------------------------------------
// C = A @ W^T + bias  (A: MxK ld=K, W: NxK ld=K, C: MxN), fp32 SIMT 64x64x16
// ---------------------------------------------------------------------------
__global__ void gemm_bias_nt(const float* __restrict__ A, const float* __restrict__ W,
                             const float* __restrict__ bias, float* __restrict__ C,
                             int M, int N, int K) {
    __shared__ float As[16][64];
    __shared__ float Bs[16][64];
    const int tid = threadIdx.x;
    const int bm = blockIdx.y * 64, bn = blockIdx.x * 64;
    const int lm = tid >> 2;
    const int lk = (tid & 3) * 4;
    const float* Ap = A + (long)(bm + lm) * K + lk;
    const float* Wp = W + (long)(bn + lm) * K + lk;
    const int tm = (tid >> 4) << 2, tn = (tid & 15) << 2;
    float acc[4][4] = {};
    for (int k0 = 0; k0 < K; k0 += 16) {
        float4 a = *(const float4*)(Ap + k0);
        float4 b = *(const float4*)(Wp + k0);
        As[lk+0][lm] = a.x; As[lk+1][lm] = a.y; As[lk+2][lm] = a.z; As[lk+3][lm] = a.w;
        Bs[lk+0][lm] = b.x; Bs[lk+1][lm] = b.y; Bs[lk+2][lm] = b.z; Bs[lk+3][lm] = b.w;
        __syncthreads();
        #pragma unroll
        for (int k = 0; k < 16; k++) {
            float4 av = *(const float4*)&As[k][tm];
            float4 bv = *(const float4*)&Bs[k][tn];
            float ar[4] = {av.x, av.y, av.z, av.w};
            float br[4] = {bv.x, bv.y, bv.z, bv.w};
            #pragma unroll
            for (int i = 0; i < 4; i++)
                #pragma unroll
                for (int j = 0; j < 4; j++)
                    acc[i][j] = fmaf(ar[i], br[j], acc[i][j]);
        }
        __syncthreads();
    }
    #pragma unroll
    for (int i = 0; i < 4; i++)
        #pragma unroll
        for (int j = 0; j < 4; j++)
            C[(long)(bm + tm + i) * N + bn + tn + j] = acc[i][j] + bias[bn + tn + j];
}

// ---------------------------------------------------------------------------
// L2-normalize rows of length HD_ (B*S rows)
// ---------------------------------------------------------------------------
__global__ void l2norm_rows(float* __restrict__ x) {
    const long base = (long)blockIdx.x * HD_;
    float ss = 0.0f;
    for (int c = threadIdx.x; c < HD_; c += 256) { float v = x[base + c]; ss += v * v; }
    ss = blockSum256(ss);
    const float inv = 1.0f / fmaxf(sqrtf(ss), 1e-12f);
    for (int c = threadIdx.x; c < HD_; c += 256) x[base + c] *= inv;
}

// ---------------------------------------------------------------------------
// current_kv output: out_kv[b][s][0][:] = k (normalized), [1][:] = v
// ---------------------------------------------------------------------------
__global__ void copy_kv(float* __restrict__ out_kv) {
    const long idx = (long)blockIdx.x * 256 + threadIdx.x;   // over B*S*HD
    const int c = (int)(idx % HD_);
    const long r = idx / HD_;                                // b*S+s
    out_kv[(r * 2) * HD_ + c]     = g_k[idx];
    out_kv[(r * 2 + 1) * HD_ + c] = g_v[idx];
}

// ---------------------------------------------------------------------------
// Flash attention, tf32 mma. MODE 0: main (xl ++ new kv, causal, rel_pos)
//                            MODE 1: external kNN (4096 keys, no mask)
// 128 threads (4 warps); block = one (b,h) x one 64-row q tile.
// Warp w handles q rows [16w,16w+16). D=64.
// ---------------------------------------------------------------------------
#define PADW 68
template<int MODE>
__global__ void __launch_bounds__(128) flash_attn(
    const float* __restrict__ q, const float* __restrict__ xl,
    const float* __restrict__ knew, const float* __restrict__ vnew,
    const float* __restrict__ kve, const float* __restrict__ rel,
    const float* __restrict__ gate, float* __restrict__ fused)
{
    __shared__ float Ks[64][PADW];   // K tile; reused as P staging after S-mma
    __shared__ float Vs[64][PADW];
    const int qt = blockIdx.x, z = blockIdx.y;
    const int b = z >> 4, h = z & 15;
    const int i0 = qt * 64;
    const int tid = threadIdx.x;
    const int w = tid >> 5, lane = tid & 31;
    const int g = lane >> 2, t = lane & 3;
    const int wr = w * 16;

    // Q fragments (resident, tf32)
    unsigned qa[8][4];
    {
        const float* q0 = q + ((long)(b * S_ + i0 + wr + g)) * HD_ + h * D_;
        const float* q8 = q0 + 8 * HD_;
        #pragma unroll
        for (int ks = 0; ks < 8; ks++) {
            qa[ks][0] = tf32u(q0[ks*8 + t]);
            qa[ks][1] = tf32u(q8[ks*8 + t]);
            qa[ks][2] = tf32u(q0[ks*8 + t + 4]);
            qa[ks][3] = tf32u(q8[ks*8 + t + 4]);
        }
    }

    float oacc[8][4];
    #pragma unroll
    for (int i = 0; i < 8; i++)
        #pragma unroll
        for (int j = 0; j < 4; j++) oacc[i][j] = 0.0f;
    float m0 = -1e30f, m1 = -1e30f, l0 = 0.0f, l1 = 0.0f;

    const int ntiles = (MODE == 0) ? (9 + qt) : 64;
    for (int jt = 0; jt < ntiles; jt++) {
        __syncthreads();   // previous iteration's P/V reads done
        const int j0 = jt * 64;
        // cooperative K/V tile load (tf32-rounded at store)
        #pragma unroll
        for (int u = 0; u < 8; u++) {
            int lin = u * 128 + tid;          // 0..1023
            int r = lin >> 4, c4 = (lin & 15) * 4;
            const float *kp, *vp;
            if (MODE == 0) {
                if (j0 + r < XL_) {
                    const float* base = xl + (((long)(b * XL_ + j0 + r)) * 2) * HD_ + h * D_ + c4;
                    kp = base; vp = base + HD_;
                } else {
                    int s = j0 + r - XL_;
                    kp = knew + ((long)(b * S_ + s)) * HD_ + h * D_ + c4;
                    vp = vnew + ((long)(b * S_ + s)) * HD_ + h * D_ + c4;
                }
            } else {
                const float* base = kve + ((long)b * ST_ + j0 + r) * (2 * HD_) + h * D_ + c4;
                kp = base; vp = base + HD_;
            }
            float4 kk = *(const float4*)kp;
            float4 vv = *(const float4*)vp;
            Ks[r][c4+0] = tf32f(kk.x); Ks[r][c4+1] = tf32f(kk.y);
            Ks[r][c4+2] = tf32f(kk.z); Ks[r][c4+3] = tf32f(kk.w);
            Vs[r][c4+0] = tf32f(vv.x); Vs[r][c4+1] = tf32f(vv.y);
            Vs[r][c4+2] = tf32f(vv.z); Vs[r][c4+3] = tf32f(vv.w);
        }
        __syncthreads();

        // S = Q @ K^T  (accum 16x64 per warp)
        float sacc[8][4];
        #pragma unroll
        for (int i = 0; i < 8; i++)
            #pragma unroll
            for (int j = 0; j < 4; j++) sacc[i][j] = 0.0f;
        #pragma unroll
        for (int ks = 0; ks < 8; ks++) {
            #pragma unroll
            for (int nf = 0; nf < 8; nf++) {
                unsigned b0 = __float_as_uint(Ks[nf*8 + g][ks*8 + t]);
                unsigned b1 = __float_as_uint(Ks[nf*8 + g][ks*8 + t + 4]);
                mma8(sacc[nf], qa[ks], b0, b1);
            }
        }

        // logits: (s + rel) * scale, causal mask on diagonal tile
        float mx0 = -1e30f, mx1 = -1e30f;
        const bool diag = (MODE == 0) && (jt == ntiles - 1);
        #pragma unroll
        for (int nf = 0; nf < 8; nf++) {
            int jc = nf * 8 + 2 * t;
            float vx, vy, vz, vw;
            if (MODE == 0) {
                const float* r0p = rel + (((long)h * S_ + i0 + wr + g) * J_) + j0 + jc;
                const float* r1p = r0p + 8 * J_;
                float2 ra = *(const float2*)r0p;
                float2 rb = *(const float2*)r1p;
                vx = (sacc[nf][0] + ra.x) * 0.125f;
                vy = (sacc[nf][1] + ra.y) * 0.125f;
                vz = (sacc[nf][2] + rb.x) * 0.125f;
                vw = (sacc[nf][3] + rb.y) * 0.125f;
                if (diag) {
                    int ir0 = wr + g, ir1 = ir0 + 8;
                    if (jc     > ir0) vx = -1e30f;
                    if (jc + 1 > ir0) vy = -1e30f;
                    if (jc     > ir1) vz = -1e30f;
                    if (jc + 1 > ir1) vw = -1e30f;
                }
            } else {
                vx = sacc[nf][0] * 0.125f;
                vy = sacc[nf][1] * 0.125f;
                vz = sacc[nf][2] * 0.125f;
                vw = sacc[nf][3] * 0.125f;
            }
            sacc[nf][0] = vx; sacc[nf][1] = vy; sacc[nf][2] = vz; sacc[nf][3] = vw;
            mx0 = fmaxf(mx0, fmaxf(vx, vy));
            mx1 = fmaxf(mx1, fmaxf(vz, vw));
        }
        mx0 = fmaxf(mx0, __shfl_xor_sync(0xffffffffu, mx0, 1));
        mx0 = fmaxf(mx0, __shfl_xor_sync(0xffffffffu, mx0, 2));
        mx1 = fmaxf(mx1, __shfl_xor_sync(0xffffffffu, mx1, 1));
        mx1 = fmaxf(mx1, __shfl_xor_sync(0xffffffffu, mx1, 2));
        const float mn0 = fmaxf(m0, mx0), mn1 = fmaxf(m1, mx1);
        const float a0 = __expf(m0 - mn0), a1 = __expf(m1 - mn1);
        m0 = mn0; m1 = mn1;
        float s0 = 0.0f, s1 = 0.0f;
        #pragma unroll
        for (int nf = 0; nf < 8; nf++) {
            float px = __expf(sacc[nf][0] - mn0), py = __expf(sacc[nf][1] - mn0);
            float pz = __expf(sacc[nf][2] - mn1), pw = __expf(sacc[nf][3] - mn1);
            s0 += px + py; s1 += pz + pw;
            sacc[nf][0] = px; sacc[nf][1] = py; sacc[nf][2] = pz; sacc[nf][3] = pw;
            oacc[nf][0] *= a0; oacc[nf][1] *= a0;
            oacc[nf][2] *= a1; oacc[nf][3] *= a1;
        }
        s0 += __shfl_xor_sync(0xffffffffu, s0, 1);
        s0 += __shfl_xor_sync(0xffffffffu, s0, 2);
        s1 += __shfl_xor_sync(0xffffffffu, s1, 1);
        s1 += __shfl_xor_sync(0xffffffffu, s1, 2);
        l0 = l0 * a0 + s0;
        l1 = l1 * a1 + s1;

        __syncthreads();   // all warps done reading Ks for S-mma
        // stage P into Ks region (each warp owns its 16 rows)
        #pragma unroll
        for (int nf = 0; nf < 8; nf++) {
            int jc = nf * 8 + 2 * t;
            Ks[wr + g][jc]       = tf32f(sacc[nf][0]);
            Ks[wr + g][jc + 1]   = tf32f(sacc[nf][1]);
            Ks[wr + g + 8][jc]   = tf32f(sacc[nf][2]);
            Ks[wr + g + 8][jc+1] = tf32f(sacc[nf][3]);
        }
        __syncwarp();
        // O += P @ V
        #pragma unroll
        for (int ks = 0; ks < 8; ks++) {
            unsigned pa[4];
            pa[0] = __float_as_uint(Ks[wr + g][ks*8 + t]);
            pa[1] = __float_as_uint(Ks[wr + g + 8][ks*8 + t]);
            pa[2] = __float_as_uint(Ks[wr + g][ks*8 + t + 4]);
            pa[3] = __float_as_uint(Ks[wr + g + 8][ks*8 + t + 4]);
            #pragma unroll
            for (int nf = 0; nf < 8; nf++) {
                unsigned b0 = __float_as_uint(Vs[ks*8 + t][nf*8 + g]);
                unsigned b1 = __float_as_uint(Vs[ks*8 + t + 4][nf*8 + g]);
                mma8(oacc[nf], pa, b0, b1);
            }
        }
    }

    // epilogue: normalize, gate, write/accumulate fused
    const float gv = gate[h];
    const float gg = 1.0f / (1.0f + __expf(-gv));
    const float f = (MODE == 0) ? gg : (1.0f - gg);
    const float inv0 = f / l0, inv1 = f / l1;
    const long base0 = ((long)(b * S_ + i0 + wr + g)) * HD_ + h * D_;
    const long base8 = base0 + 8 * HD_;
    #pragma unroll
    for (int nf = 0; nf < 8; nf++) {
        int jc = nf * 8 + 2 * t;
        if (MODE == 0) {
            float2 r0v = { oacc[nf][0] * inv0, oacc[nf][1] * inv0 };
            float2 r1v = { oacc[nf][2] * inv1, oacc[nf][3] * inv1 };
            *(float2*)&fused[base0 + jc] = r0v;
            *(float2*)&fused[base8 + jc] = r1v;
        } else {
            float2 o0 = *(const float2*)&fused[base0 + jc];
            float2 o1 = *(const float2*)&fused[base8 + jc];
            o0.x += oacc[nf][0] * inv0; o0.y += oacc[nf][1] * inv0;
            o1.x += oacc[nf][2] * inv1; o1.y += oacc[nf][3] * inv1;
            *(float2*)&fused[base0 + jc] = o0;
            *(float2*)&fused[base8 + jc] = o1;
        }
    }
}

// ---------------------------------------------------------------------------
extern "C" void kernel_launch(void* const* d_in, const int* in_sizes, int n_in,
                              void* d_out, int out_size) {
    const float* input = (const float*)d_in[0];
    const float* rel   = (const float*)d_in[1];
    const float* xl    = (const float*)d_in[2];
    const float* kve   = (const float*)d_in[3];
    const float* Wq = (const float*)d_in[4];  const float* bq = (const float*)d_in[5];
    const float* Wk = (const float*)d_in[6];  const float* bk = (const float*)d_in[7];
    const float* Wv = (const float*)d_in[8];  const float* bv = (const float*)d_in[9];
    const float* Wo = (const float*)d_in[10]; const float* bo = (const float*)d_in[11];
    const float* gate = (const float*)d_in[12];

    float* out = (float*)d_out;                    // (B,S,E)
    float* out_kv = out + (long)B_ * S_ * E_;      // (B,S,2,HD)

    float *q, *k, *v, *fused;
    cudaGetSymbolAddress((void**)&q, g_q);
    cudaGetSymbolAddress((void**)&k, g_k);
    cudaGetSymbolAddress((void**)&v, g_v);
    cudaGetSymbolAddress((void**)&fused, g_fused);

    const dim3 t(256);
    const dim3 gproj(E_ / 64, MROWS / 64);

    // Projections (fp32 SIMT)
    gemm_bias_nt<<<gproj, t>>>(input, Wq, bq, q, MROWS, HD_, E_);
    gemm_bias_nt<<<gproj, t>>>(input, Wk, bk, k, MROWS, HD_, E_);
    gemm_bias_nt<<<gproj, t>>>(input, Wv, bv, v, MROWS, HD_, E_);
    // L2 norm over full HD (before head split, per reference)
    l2norm_rows<<<MROWS, t>>>(q);
    l2norm_rows<<<MROWS, t>>>(k);
    // current_kv output
    copy_kv<<<(B_ * S_ * HD_) / 256, t>>>(out_kv);

    // Fused flash attention (tf32 tensor cores)
    flash_attn<0><<<dim3(S_ / 64, B_ * H_), dim3(128)>>>(q, xl, k, v, kve, rel, gate, fused);
    flash_attn<1><<<dim3(S_ / 64, B_ * H_), dim3(128)>>>(q, xl, k, v, kve, rel, gate, fused);

    // Output projection
    gemm_bias_nt<<<gproj, t>>>(fused, Wo, bo, out, MROWS, E_, HD_);
}

// round 3
// speedup vs baseline: 2.3634x; 1.2088x over previous
#include <cuda_runtime.h>
#include <math.h>
#include <float.h>

// Problem constants
#define B_    4
#define S_    512
#define E_    1024
#define H_    16
#define D_    64
#define HD_   1024
#define XL_   512
#define J_    1024      // XL + S
#define TOPK_ 8
#define ST_   4096      // S * TOPK
#define MROWS 2048      // B * S

// Static scratch (no allocations allowed)
__device__ float g_q[B_*S_*HD_];
__device__ float g_k[B_*S_*HD_];
__device__ float g_v[B_*S_*HD_];
__device__ float g_fused[B_*S_*HD_];

// ---------------------------------------------------------------------------
// tf32 helpers
// ---------------------------------------------------------------------------
__device__ __forceinline__ unsigned tf32u(float x) {
    unsigned u;
    asm("cvt.rna.tf32.f32 %0, %1;" : "=r"(u) : "f"(x));
    return u;
}
__device__ __forceinline__ float tf32f(float x) { return __uint_as_float(tf32u(x)); }

__device__ __forceinline__ void mma8(float* c, const unsigned* a, unsigned b0, unsigned b1) {
    asm volatile(
        "mma.sync.aligned.m16n8k8.row.col.f32.tf32.tf32.f32 "
        "{%0,%1,%2,%3},{%4,%5,%6,%7},{%8,%9},{%0,%1,%2,%3};"
        : "+f"(c[0]), "+f"(c[1]), "+f"(c[2]), "+f"(c[3])
        : "r"(a[0]), "r"(a[1]), "r"(a[2]), "r"(a[3]), "r"(b0), "r"(b1));
}

// ---------------------------------------------------------------------------
// Block reduction (256 threads)
// ---------------------------------------------------------------------------
__device__ __forceinline__ float blockSum256(float v) {
    __shared__ float sh[8];
    #pragma unroll
    for (int o = 16; o > 0; o >>= 1) v += __shfl_xor_sync(0xffffffffu, v, o);
    if ((threadIdx.x & 31) == 0) sh[threadIdx.x >> 5] = v;
    __syncthreads();
    if (threadIdx.x < 32) {
        float w = (threadIdx.x < 8) ? sh[threadIdx.x] : 0.0f;
        #pragma unroll
        for (int o = 4; o > 0; o >>= 1) w += __shfl_xor_sync(0xffffffffu, w, o);
        if (threadIdx.x == 0) sh[0] = w;
    }
    __syncthreads();
    float r = sh[0];
    __syncthreads();
    return r;
}

// ---------------------------------------------------------------------------
// C = A @ W^T + bias via 3xTF32 tensor-core GEMM (~fp32 accuracy)
// A: MxK row-major, W: NxK row-major, C: MxN.
// Block tile 128x128x16, 256 threads = 8 warps (2x4), warp tile 64x32.
// ---------------------------------------------------------------------------
#define GSTR 136   // BM + 8: bank-conflict-free fragment loads
__global__ void __launch_bounds__(256) gemm3_tf32_nt(
    const float* __restrict__ A, const float* __restrict__ W,
    const float* __restrict__ bias, float* __restrict__ C,
    int M, int N, int K)
{
    __shared__ float Ah[16][GSTR], Al[16][GSTR], Bh[16][GSTR], Bl[16][GSTR];
    const int tid = threadIdx.x;
    const int bm = blockIdx.y * 128, bn = blockIdx.x * 128;
    const int w = tid >> 5, lane = tid & 31;
    const int g = lane >> 2, t = lane & 3;
    const int wm = (w & 1) * 64, wn = (w >> 1) * 32;

    // global load assignment: row r, 8 cols starting at c0
    const int r = tid >> 1, c0 = (tid & 1) * 8;
    const float* Ap = A + (long)(bm + r) * K + c0;
    const float* Wp = W + (long)(bn + r) * K + c0;

    float acc[4][4][4];
    #pragma unroll
    for (int mi = 0; mi < 4; mi++)
        #pragma unroll
        for (int ni = 0; ni < 4; ni++)
            #pragma unroll
            for (int x = 0; x < 4; x++) acc[mi][ni][x] = 0.0f;

    for (int k0 = 0; k0 < K; k0 += 16) {
        float4 a0 = *(const float4*)(Ap + k0);
        float4 a1 = *(const float4*)(Ap + k0 + 4);
        float4 b0 = *(const float4*)(Wp + k0);
        float4 b1 = *(const float4*)(Wp + k0 + 4);
        __syncthreads();
        {
            const float av[8] = {a0.x,a0.y,a0.z,a0.w,a1.x,a1.y,a1.z,a1.w};
            const float bv[8] = {b0.x,b0.y,b0.z,b0.w,b1.x,b1.y,b1.z,b1.w};
            #pragma unroll
            for (int j = 0; j < 8; j++) {
                float ahv = tf32f(av[j]);
                float bhv = tf32f(bv[j]);
                Ah[c0 + j][r] = ahv; Al[c0 + j][r] = av[j] - ahv;
                Bh[c0 + j][r] = bhv; Bl[c0 + j][r] = bv[j] - bhv;
            }
        }
        __syncthreads();

        #pragma unroll
        for (int kk = 0; kk < 16; kk += 8) {
            unsigned ah[4][4], al[4][4], bh[4][2], bl[4][2];
            #pragma unroll
            for (int mi = 0; mi < 4; mi++) {
                const int mb = wm + mi * 16;
                ah[mi][0] = __float_as_uint(Ah[kk + t][mb + g]);
                ah[mi][1] = __float_as_uint(Ah[kk + t][mb + g + 8]);
                ah[mi][2] = __float_as_uint(Ah[kk + t + 4][mb + g]);
                ah[mi][3] = __float_as_uint(Ah[kk + t + 4][mb + g + 8]);
                al[mi][0] = __float_as_uint(Al[kk + t][mb + g]);
                al[mi][1] = __float_as_uint(Al[kk + t][mb + g + 8]);
                al[mi][2] = __float_as_uint(Al[kk + t + 4][mb + g]);
                al[mi][3] = __float_as_uint(Al[kk + t + 4][mb + g + 8]);
            }
            #pragma unroll
            for (int ni = 0; ni < 4; ni++) {
                const int nb = wn + ni * 8;
                bh[ni][0] = __float_as_uint(Bh[kk + t][nb + g]);
                bh[ni][1] = __float_as_uint(Bh[kk + t + 4][nb + g]);
                bl[ni][0] = __float_as_uint(Bl[kk + t][nb + g]);
                bl[ni][1] = __float_as_uint(Bl[kk + t + 4][nb + g]);
            }
            #pragma unroll
            for (int mi = 0; mi < 4; mi++)
                #pragma unroll
                for (int ni = 0; ni < 4; ni++) {
                    mma8(acc[mi][ni], ah[mi], bh[ni][0], bh[ni][1]);
                    mma8(acc[mi][ni], ah[mi], bl[ni][0], bl[ni][1]);
                    mma8(acc[mi][ni], al[mi], bh[ni][0], bh[ni][1]);
                }
        }
    }

    // epilogue
    #pragma unroll
    for (int mi = 0; mi < 4; mi++) {
        const int r0 = bm + wm + mi * 16 + g;
        #pragma unroll
        for (int ni = 0; ni < 4; ni++) {
            const int col = bn + wn + ni * 8 + 2 * t;
            const float bx = bias[col], by = bias[col + 1];
            float2 v0 = { acc[mi][ni][0] + bx, acc[mi][ni][1] + by };
            float2 v1 = { acc[mi][ni][2] + bx, acc[mi][ni][3] + by };
            *(float2*)&C[(long)r0 * N + col] = v0;
            *(float2*)&C[(long)(r0 + 8) * N + col] = v1;
        }
    }
}

// ---------------------------------------------------------------------------
// L2-normalize rows of length HD_ (B*S rows)
// ---------------------------------------------------------------------------
__global__ void l2norm_rows(float* __restrict__ x) {
    const long base = (long)blockIdx.x * HD_;
    float ss = 0.0f;
    for (int c = threadIdx.x; c < HD_; c += 256) { float v = x[base + c]; ss += v * v; }
    ss = blockSum256(ss);
    const float inv = 1.0f / fmaxf(sqrtf(ss), 1e-12f);
    for (int c = threadIdx.x; c < HD_; c += 256) x[base + c] *= inv;
}

// ---------------------------------------------------------------------------
// current_kv output: out_kv[b][s][0][:] = k (normalized), [1][:] = v
// ---------------------------------------------------------------------------
__global__ void copy_kv(float* __restrict__ out_kv) {
    const long idx = (long)blockIdx.x * 256 + threadIdx.x;   // over B*S*HD
    const int c = (int)(idx % HD_);
    const long r = idx / HD_;                                // b*S+s
    out_kv[(r * 2) * HD_ + c]     = g_k[idx];
    out_kv[(r * 2 + 1) * HD_ + c] = g_v[idx];
}

// ---------------------------------------------------------------------------
// Flash attention, tf32 mma. MODE 0: main (xl ++ new kv, causal, rel_pos)
//                            MODE 1: external kNN (4096 keys, no mask)
// ---------------------------------------------------------------------------
#define PADW 68
template<int MODE>
__global__ void __launch_bounds__(128) flash_attn(
    const float* __restrict__ q, const float* __restrict__ xl,
    const float* __restrict__ knew, const float* __restrict__ vnew,
    const float* __restrict__ kve, const float* __restrict__ rel,
    const float* __restrict__ gate, float* __restrict__ fused)
{
    __shared__ float Ks[64][PADW];   // K tile; reused as P staging after S-mma
    __shared__ float Vs[64][PADW];
    const int qt = blockIdx.x, z = blockIdx.y;
    const int b = z >> 4, h = z & 15;
    const int i0 = qt * 64;
    const int tid = threadIdx.x;
    const int w = tid >> 5, lane = tid & 31;
    const int g = lane >> 2, t = lane & 3;
    const int wr = w * 16;

    // Q fragments (resident, tf32)
    unsigned qa[8][4];
    {
        const float* q0 = q + ((long)(b * S_ + i0 + wr + g)) * HD_ + h * D_;
        const float* q8 = q0 + 8 * HD_;
        #pragma unroll
        for (int ks = 0; ks < 8; ks++) {
            qa[ks][0] = tf32u(q0[ks*8 + t]);
            qa[ks][1] = tf32u(q8[ks*8 + t]);
            qa[ks][2] = tf32u(q0[ks*8 + t + 4]);
            qa[ks][3] = tf32u(q8[ks*8 + t + 4]);
        }
    }

    float oacc[8][4];
    #pragma unroll
    for (int i = 0; i < 8; i++)
        #pragma unroll
        for (int j = 0; j < 4; j++) oacc[i][j] = 0.0f;
    float m0 = -1e30f, m1 = -1e30f, l0 = 0.0f, l1 = 0.0f;

    const int ntiles = (MODE == 0) ? (9 + qt) : 64;
    for (int jt = 0; jt < ntiles; jt++) {
        __syncthreads();   // previous iteration's P/V reads done
        const int j0 = jt * 64;
        // cooperative K/V tile load (tf32-rounded at store)
        #pragma unroll
        for (int u = 0; u < 8; u++) {
            int lin = u * 128 + tid;          // 0..1023
            int r = lin >> 4, c4 = (lin & 15) * 4;
            const float *kp, *vp;
            if (MODE == 0) {
                if (j0 + r < XL_) {
                    const float* base = xl + (((long)(b * XL_ + j0 + r)) * 2) * HD_ + h * D_ + c4;
                    kp = base; vp = base + HD_;
                } else {
                    int s = j0 + r - XL_;
                    kp = knew + ((long)(b * S_ + s)) * HD_ + h * D_ + c4;
                    vp = vnew + ((long)(b * S_ + s)) * HD_ + h * D_ + c4;
                }
            } else {
                const float* base = kve + ((long)b * ST_ + j0 + r) * (2 * HD_) + h * D_ + c4;
                kp = base; vp = base + HD_;
            }
            float4 kk = *(const float4*)kp;
            float4 vv = *(const float4*)vp;
            Ks[r][c4+0] = tf32f(kk.x); Ks[r][c4+1] = tf32f(kk.y);
            Ks[r][c4+2] = tf32f(kk.z); Ks[r][c4+3] = tf32f(kk.w);
            Vs[r][c4+0] = tf32f(vv.x); Vs[r][c4+1] = tf32f(vv.y);
            Vs[r][c4+2] = tf32f(vv.z); Vs[r][c4+3] = tf32f(vv.w);
        }
        __syncthreads();

        // S = Q @ K^T  (accum 16x64 per warp)
        float sacc[8][4];
        #pragma unroll
        for (int i = 0; i < 8; i++)
            #pragma unroll
            for (int j = 0; j < 4; j++) sacc[i][j] = 0.0f;
        #pragma unroll
        for (int ks = 0; ks < 8; ks++) {
            #pragma unroll
            for (int nf = 0; nf < 8; nf++) {
                unsigned b0 = __float_as_uint(Ks[nf*8 + g][ks*8 + t]);
                unsigned b1 = __float_as_uint(Ks[nf*8 + g][ks*8 + t + 4]);
                mma8(sacc[nf], qa[ks], b0, b1);
            }
        }

        // logits: (s + rel) * scale, causal mask on diagonal tile
        float mx0 = -1e30f, mx1 = -1e30f;
        const bool diag = (MODE == 0) && (jt == ntiles - 1);
        #pragma unroll
        for (int nf = 0; nf < 8; nf++) {
            int jc = nf * 8 + 2 * t;
            float vx, vy, vz, vw;
            if (MODE == 0) {
                const float* r0p = rel + (((long)h * S_ + i0 + wr + g) * J_) + j0 + jc;
                const float* r1p = r0p + 8 * J_;
                float2 ra = *(const float2*)r0p;
                float2 rb = *(const float2*)r1p;
                vx = (sacc[nf][0] + ra.x) * 0.125f;
                vy = (sacc[nf][1] + ra.y) * 0.125f;
                vz = (sacc[nf][2] + rb.x) * 0.125f;
                vw = (sacc[nf][3] + rb.y) * 0.125f;
                if (diag) {
                    int ir0 = wr + g, ir1 = ir0 + 8;
                    if (jc     > ir0) vx = -1e30f;
                    if (jc + 1 > ir0) vy = -1e30f;
                    if (jc     > ir1) vz = -1e30f;
                    if (jc + 1 > ir1) vw = -1e30f;
                }
            } else {
                vx = sacc[nf][0] * 0.125f;
                vy = sacc[nf][1] * 0.125f;
                vz = sacc[nf][2] * 0.125f;
                vw = sacc[nf][3] * 0.125f;
            }
            sacc[nf][0] = vx; sacc[nf][1] = vy; sacc[nf][2] = vz; sacc[nf][3] = vw;
            mx0 = fmaxf(mx0, fmaxf(vx, vy));
            mx1 = fmaxf(mx1, fmaxf(vz, vw));
        }
        mx0 = fmaxf(mx0, __shfl_xor_sync(0xffffffffu, mx0, 1));
        mx0 = fmaxf(mx0, __shfl_xor_sync(0xffffffffu, mx0, 2));
        mx1 = fmaxf(mx1, __shfl_xor_sync(0xffffffffu, mx1, 1));
        mx1 = fmaxf(mx1, __shfl_xor_sync(0xffffffffu, mx1, 2));
        const float mn0 = fmaxf(m0, mx0), mn1 = fmaxf(m1, mx1);
        const float a0 = __expf(m0 - mn0), a1 = __expf(m1 - mn1);
        m0 = mn0; m1 = mn1;
        float s0 = 0.0f, s1 = 0.0f;
        #pragma unroll
        for (int nf = 0; nf < 8; nf++) {
            float px = __expf(sacc[nf][0] - mn0), py = __expf(sacc[nf][1] - mn0);
            float pz = __expf(sacc[nf][2] - mn1), pw = __expf(sacc[nf][3] - mn1);
            s0 += px + py; s1 += pz + pw;
            sacc[nf][0] = px; sacc[nf][1] = py; sacc[nf][2] = pz; sacc[nf][3] = pw;
            oacc[nf][0] *= a0; oacc[nf][1] *= a0;
            oacc[nf][2] *= a1; oacc[nf][3] *= a1;
        }
        s0 += __shfl_xor_sync(0xffffffffu, s0, 1);
        s0 += __shfl_xor_sync(0xffffffffu, s0, 2);
        s1 += __shfl_xor_sync(0xffffffffu, s1, 1);
        s1 += __shfl_xor_sync(0xffffffffu, s1, 2);
        l0 = l0 * a0 + s0;
        l1 = l1 * a1 + s1;

        __syncthreads();   // all warps done reading Ks for S-mma
        // stage P into Ks region (each warp owns its 16 rows)
        #pragma unroll
        for (int nf = 0; nf < 8; nf++) {
            int jc = nf * 8 + 2 * t;
            Ks[wr + g][jc]       = tf32f(sacc[nf][0]);
            Ks[wr + g][jc + 1]   = tf32f(sacc[nf][1]);
            Ks[wr + g + 8][jc]   = tf32f(sacc[nf][2]);
            Ks[wr + g + 8][jc+1] = tf32f(sacc[nf][3]);
        }
        __syncwarp();
        // O += P @ V
        #pragma unroll
        for (int ks = 0; ks < 8; ks++) {
            unsigned pa[4];
            pa[0] = __float_as_uint(Ks[wr + g][ks*8 + t]);
            pa[1] = __float_as_uint(Ks[wr + g + 8][ks*8 + t]);
            pa[2] = __float_as_uint(Ks[wr + g][ks*8 + t + 4]);
            pa[3] = __float_as_uint(Ks[wr + g + 8][ks*8 + t + 4]);
            #pragma unroll
            for (int nf = 0; nf < 8; nf++) {
                unsigned b0 = __float_as_uint(Vs[ks*8 + t][nf*8 + g]);
                unsigned b1 = __float_as_uint(Vs[ks*8 + t + 4][nf*8 + g]);
                mma8(oacc[nf], pa, b0, b1);
            }
        }
    }

    // epilogue: normalize, gate, write/accumulate fused
    const float gv = gate[h];
    const float gg = 1.0f / (1.0f + __expf(-gv));
    const float f = (MODE == 0) ? gg : (1.0f - gg);
    const float inv0 = f / l0, inv1 = f / l1;
    const long base0 = ((long)(b * S_ + i0 + wr + g)) * HD_ + h * D_;
    const long base8 = base0 + 8 * HD_;
    #pragma unroll
    for (int nf = 0; nf < 8; nf++) {
        int jc = nf * 8 + 2 * t;
        if (MODE == 0) {
            float2 r0v = { oacc[nf][0] * inv0, oacc[nf][1] * inv0 };
            float2 r1v = { oacc[nf][2] * inv1, oacc[nf][3] * inv1 };
            *(float2*)&fused[base0 + jc] = r0v;
            *(float2*)&fused[base8 + jc] = r1v;
        } else {
            float2 o0 = *(const float2*)&fused[base0 + jc];
            float2 o1 = *(const float2*)&fused[base8 + jc];
            o0.x += oacc[nf][0] * inv0; o0.y += oacc[nf][1] * inv0;
            o1.x += oacc[nf][2] * inv1; o1.y += oacc[nf][3] * inv1;
            *(float2*)&fused[base0 + jc] = o0;
            *(float2*)&fused[base8 + jc] = o1;
        }
    }
}

// ---------------------------------------------------------------------------
extern "C" void kernel_launch(void* const* d_in, const int* in_sizes, int n_in,
                              void* d_out, int out_size) {
    const float* input = (const float*)d_in[0];
    const float* rel   = (const float*)d_in[1];
    const float* xl    = (const float*)d_in[2];
    const float* kve   = (const float*)d_in[3];
    const float* Wq = (const float*)d_in[4];  const float* bq = (const float*)d_in[5];
    const float* Wk = (const float*)d_in[6];  const float* bk = (const float*)d_in[7];
    const float* Wv = (const float*)d_in[8];  const float* bv = (const float*)d_in[9];
    const float* Wo = (const float*)d_in[10]; const float* bo = (const float*)d_in[11];
    const float* gate = (const float*)d_in[12];

    float* out = (float*)d_out;                    // (B,S,E)
    float* out_kv = out + (long)B_ * S_ * E_;      // (B,S,2,HD)

    float *q, *k, *v, *fused;
    cudaGetSymbolAddress((void**)&q, g_q);
    cudaGetSymbolAddress((void**)&k, g_k);
    cudaGetSymbolAddress((void**)&v, g_v);
    cudaGetSymbolAddress((void**)&fused, g_fused);

    const dim3 t(256);
    const dim3 gproj(E_ / 128, MROWS / 128);       // 8 x 16 blocks

    // Projections (3xTF32 tensor cores, ~fp32 accuracy)
    gemm3_tf32_nt<<<gproj, t>>>(input, Wq, bq, q, MROWS, HD_, E_);
    gemm3_tf32_nt<<<gproj, t>>>(input, Wk, bk, k, MROWS, HD_, E_);
    gemm3_tf32_nt<<<gproj, t>>>(input, Wv, bv, v, MROWS, HD_, E_);
    // L2 norm over full HD (before head split, per reference)
    l2norm_rows<<<MROWS, t>>>(q);
    l2norm_rows<<<MROWS, t>>>(k);
    // current_kv output
    copy_kv<<<(B_ * S_ * HD_) / 256, t>>>(out_kv);

    // Fused flash attention (tf32 tensor cores)
    flash_attn<0><<<dim3(S_ / 64, B_ * H_), dim3(128)>>>(q, xl, k, v, kve, rel, gate, fused);
    flash_attn<1><<<dim3(S_ / 64, B_ * H_), dim3(128)>>>(q, xl, k, v, kve, rel, gate, fused);

    // Output projection
    gemm3_tf32_nt<<<gproj, t>>>(fused, Wo, bo, out, MROWS, E_, HD_);
}

// round 4
// speedup vs baseline: 2.4528x; 1.0378x over previous
#include <cuda_runtime.h>
#include <math.h>
#include <float.h>

// Problem constants
#define B_    4
#define S_    512
#define E_    1024
#define H_    16
#define D_    64
#define HD_   1024
#define XL_   512
#define J_    1024      // XL + S
#define TOPK_ 8
#define ST_   4096      // S * TOPK
#define MROWS 2048      // B * S

// Static scratch (no allocations allowed)
__device__ float g_q[B_*S_*HD_];
__device__ float g_k[B_*S_*HD_];
__device__ float g_v[B_*S_*HD_];
__device__ float g_fused[B_*S_*HD_];
__device__ float g_ext[B_*S_*HD_];

// ---------------------------------------------------------------------------
// Helpers
// ---------------------------------------------------------------------------
__device__ __forceinline__ unsigned tf32u(float x) {
    unsigned u;
    asm("cvt.rna.tf32.f32 %0, %1;" : "=r"(u) : "f"(x));
    return u;
}
__device__ __forceinline__ float tf32f(float x) { return __uint_as_float(tf32u(x)); }

__device__ __forceinline__ void mma8(float* c, const unsigned* a, unsigned b0, unsigned b1) {
    asm volatile(
        "mma.sync.aligned.m16n8k8.row.col.f32.tf32.tf32.f32 "
        "{%0,%1,%2,%3},{%4,%5,%6,%7},{%8,%9},{%0,%1,%2,%3};"
        : "+f"(c[0]), "+f"(c[1]), "+f"(c[2]), "+f"(c[3])
        : "r"(a[0]), "r"(a[1]), "r"(a[2]), "r"(a[3]), "r"(b0), "r"(b1));
}

__device__ __forceinline__ unsigned smaddr(const void* p) {
    return (unsigned)__cvta_generic_to_shared(p);
}
__device__ __forceinline__ void cpasync16(unsigned s, const void* g) {
    asm volatile("cp.async.cg.shared.global [%0], [%1], 16;" :: "r"(s), "l"(g));
}

__device__ __forceinline__ float4 f4add(float4 a, float4 b) {
    return make_float4(a.x + b.x, a.y + b.y, a.z + b.z, a.w + b.w);
}

__device__ __forceinline__ float blockSum256(float v) {
    __shared__ float sh[8];
    #pragma unroll
    for (int o = 16; o > 0; o >>= 1) v += __shfl_xor_sync(0xffffffffu, v, o);
    if ((threadIdx.x & 31) == 0) sh[threadIdx.x >> 5] = v;
    __syncthreads();
    if (threadIdx.x < 32) {
        float w = (threadIdx.x < 8) ? sh[threadIdx.x] : 0.0f;
        #pragma unroll
        for (int o = 4; o > 0; o >>= 1) w += __shfl_xor_sync(0xffffffffu, w, o);
        if (threadIdx.x == 0) sh[0] = w;
    }
    __syncthreads();
    float r = sh[0];
    __syncthreads();
    return r;
}

// ---------------------------------------------------------------------------
// 3xTF32 GEMM body: C = (A [+ A2]) @ W^T + bias.  Tile 128x128x16, 256 thr.
// ---------------------------------------------------------------------------
#define GSTR 136
__device__ __forceinline__ void gemm3_body(
    const float* __restrict__ A, const float* __restrict__ A2,
    const float* __restrict__ W, const float* __restrict__ bias,
    float* __restrict__ C, int bm, int bn, int N, int K)
{
    __shared__ float Ah[16][GSTR], Al[16][GSTR], Bh[16][GSTR], Bl[16][GSTR];
    const int tid = threadIdx.x;
    const int w = tid >> 5, lane = tid & 31;
    const int g = lane >> 2, t = lane & 3;
    const int wm = (w & 1) * 64, wn = (w >> 1) * 32;

    const int r = tid >> 1, c0 = (tid & 1) * 8;
    const float* Ap = A + (long)(bm + r) * K + c0;
    const float* A2p = A2 ? A2 + (long)(bm + r) * K + c0 : (const float*)0;
    const float* Wp = W + (long)(bn + r) * K + c0;

    float acc[4][4][4];
    #pragma unroll
    for (int mi = 0; mi < 4; mi++)
        #pragma unroll
        for (int ni = 0; ni < 4; ni++)
            #pragma unroll
            for (int x = 0; x < 4; x++) acc[mi][ni][x] = 0.0f;

    // prefetch first k-chunk
    float4 pa0 = *(const float4*)(Ap), pa1 = *(const float4*)(Ap + 4);
    float4 pb0 = *(const float4*)(Wp), pb1 = *(const float4*)(Wp + 4);
    if (A2) { pa0 = f4add(pa0, *(const float4*)(A2p)); pa1 = f4add(pa1, *(const float4*)(A2p + 4)); }

    for (int k0 = 0; k0 < K; k0 += 16) {
        float4 na0, na1, nb0, nb1;
        const bool more = (k0 + 16 < K);
        if (more) {
            na0 = *(const float4*)(Ap + k0 + 16); na1 = *(const float4*)(Ap + k0 + 20);
            nb0 = *(const float4*)(Wp + k0 + 16); nb1 = *(const float4*)(Wp + k0 + 20);
            if (A2) { na0 = f4add(na0, *(const float4*)(A2p + k0 + 16));
                      na1 = f4add(na1, *(const float4*)(A2p + k0 + 20)); }
        }
        __syncthreads();
        {
            const float av[8] = {pa0.x,pa0.y,pa0.z,pa0.w,pa1.x,pa1.y,pa1.z,pa1.w};
            const float bv[8] = {pb0.x,pb0.y,pb0.z,pb0.w,pb1.x,pb1.y,pb1.z,pb1.w};
            #pragma unroll
            for (int j = 0; j < 8; j++) {
                float ahv = tf32f(av[j]);
                float bhv = tf32f(bv[j]);
                Ah[c0 + j][r] = ahv; Al[c0 + j][r] = av[j] - ahv;
                Bh[c0 + j][r] = bhv; Bl[c0 + j][r] = bv[j] - bhv;
            }
        }
        __syncthreads();

        #pragma unroll
        for (int kk = 0; kk < 16; kk += 8) {
            unsigned ah[4][4], al[4][4], bh[4][2], bl[4][2];
            #pragma unroll
            for (int mi = 0; mi < 4; mi++) {
                const int mb = wm + mi * 16;
                ah[mi][0] = __float_as_uint(Ah[kk + t][mb + g]);
                ah[mi][1] = __float_as_uint(Ah[kk + t][mb + g + 8]);
                ah[mi][2] = __float_as_uint(Ah[kk + t + 4][mb + g]);
                ah[mi][3] = __float_as_uint(Ah[kk + t + 4][mb + g + 8]);
                al[mi][0] = __float_as_uint(Al[kk + t][mb + g]);
                al[mi][1] = __float_as_uint(Al[kk + t][mb + g + 8]);
                al[mi][2] = __float_as_uint(Al[kk + t + 4][mb + g]);
                al[mi][3] = __float_as_uint(Al[kk + t + 4][mb + g + 8]);
            }
            #pragma unroll
            for (int ni = 0; ni < 4; ni++) {
                const int nb = wn + ni * 8;
                bh[ni][0] = __float_as_uint(Bh[kk + t][nb + g]);
                bh[ni][1] = __float_as_uint(Bh[kk + t + 4][nb + g]);
                bl[ni][0] = __float_as_uint(Bl[kk + t][nb + g]);
                bl[ni][1] = __float_as_uint(Bl[kk + t + 4][nb + g]);
            }
            #pragma unroll
            for (int mi = 0; mi < 4; mi++)
                #pragma unroll
                for (int ni = 0; ni < 4; ni++) {
                    mma8(acc[mi][ni], ah[mi], bh[ni][0], bh[ni][1]);
                    mma8(acc[mi][ni], ah[mi], bl[ni][0], bl[ni][1]);
                    mma8(acc[mi][ni], al[mi], bh[ni][0], bh[ni][1]);
                }
        }
        pa0 = na0; pa1 = na1; pb0 = nb0; pb1 = nb1;
    }

    #pragma unroll
    for (int mi = 0; mi < 4; mi++) {
        const int r0 = bm + wm + mi * 16 + g;
        #pragma unroll
        for (int ni = 0; ni < 4; ni++) {
            const int col = bn + wn + ni * 8 + 2 * t;
            const float bx = bias[col], by = bias[col + 1];
            float2 v0 = { acc[mi][ni][0] + bx, acc[mi][ni][1] + by };
            float2 v1 = { acc[mi][ni][2] + bx, acc[mi][ni][3] + by };
            *(float2*)&C[(long)r0 * N + col] = v0;
            *(float2*)&C[(long)(r0 + 8) * N + col] = v1;
        }
    }
}

// Fused Q/K/V projection: grid (24, 16); blockIdx.x/8 picks matrix
__global__ void __launch_bounds__(256) gemm3_qkv(
    const float* __restrict__ A,
    const float* __restrict__ Wq, const float* __restrict__ Wk, const float* __restrict__ Wv,
    const float* __restrict__ bq, const float* __restrict__ bk, const float* __restrict__ bv,
    float* __restrict__ q, float* __restrict__ k, float* __restrict__ v)
{
    const int which = blockIdx.x >> 3;
    const int bn = (blockIdx.x & 7) * 128;
    const int bm = blockIdx.y * 128;
    const float* W = (which == 0) ? Wq : (which == 1) ? Wk : Wv;
    const float* bias = (which == 0) ? bq : (which == 1) ? bk : bv;
    float* C = (which == 0) ? q : (which == 1) ? k : v;
    gemm3_body(A, (const float*)0, W, bias, C, bm, bn, HD_, E_);
}

// Generic (used for output projection with A2 = g_ext)
__global__ void __launch_bounds__(256) gemm3_nt(
    const float* __restrict__ A, const float* __restrict__ A2,
    const float* __restrict__ W, const float* __restrict__ bias,
    float* __restrict__ C, int N, int K)
{
    gemm3_body(A, A2, W, bias, C, blockIdx.y * 128, blockIdx.x * 128, N, K);
}

// ---------------------------------------------------------------------------
// L2-normalize rows of length HD_
// ---------------------------------------------------------------------------
__global__ void l2norm_rows(float* __restrict__ x) {
    const long base = (long)blockIdx.x * HD_;
    float ss = 0.0f;
    for (int c = threadIdx.x; c < HD_; c += 256) { float v = x[base + c]; ss += v * v; }
    ss = blockSum256(ss);
    const float inv = 1.0f / fmaxf(sqrtf(ss), 1e-12f);
    for (int c = threadIdx.x; c < HD_; c += 256) x[base + c] *= inv;
}

__global__ void copy_kv(float* __restrict__ out_kv) {
    const long idx = (long)blockIdx.x * 256 + threadIdx.x;
    const int c = (int)(idx % HD_);
    const long r = idx / HD_;
    out_kv[(r * 2) * HD_ + c]     = g_k[idx];
    out_kv[(r * 2 + 1) * HD_ + c] = g_v[idx];
}

// ---------------------------------------------------------------------------
// Flash v2: 128-row q tiles, 256 threads, cp.async double-buffered K/V.
// blockIdx.z = 0: main (causal + rel_pos) -> outMain = g * qkv
// blockIdx.z = 1: external kNN            -> outExt  = (1-g) * qkv_ext
// ---------------------------------------------------------------------------
#define PADW 68
#define TILE_F (64 * PADW)
#define FLASH_SMEM ((4 * TILE_F + 128 * PADW) * 4)   // 104448 bytes

__global__ void __launch_bounds__(256) flash2(
    const float* __restrict__ q, const float* __restrict__ xl,
    const float* __restrict__ knew, const float* __restrict__ vnew,
    const float* __restrict__ kve, const float* __restrict__ rel,
    const float* __restrict__ gate,
    float* __restrict__ outMain, float* __restrict__ outExt)
{
    extern __shared__ float smf[];
    float* Kb = smf;                     // 2 x [64][PADW]
    float* Vb = smf + 2 * TILE_F;        // 2 x [64][PADW]
    float* Pb = smf + 4 * TILE_F;        // [128][PADW]

    const int MODE = blockIdx.z;
    const int qt = blockIdx.x, z = blockIdx.y;
    const int b = z >> 4, h = z & 15;
    const int i0 = qt * 128;
    const int tid = threadIdx.x;
    const int w = tid >> 5, lane = tid & 31;
    const int g = lane >> 2, t = lane & 3;
    const int wr = w * 16;

    const int ntiles = (MODE == 0) ? (10 + 2 * qt) : 64;

    // Q fragments (resident, tf32)
    unsigned qa[8][4];
    {
        const float* q0 = q + ((long)(b * S_ + i0 + wr + g)) * HD_ + h * D_;
        const float* q8 = q0 + 8 * HD_;
        #pragma unroll
        for (int ks = 0; ks < 8; ks++) {
            qa[ks][0] = tf32u(q0[ks*8 + t]);
            qa[ks][1] = tf32u(q8[ks*8 + t]);
            qa[ks][2] = tf32u(q0[ks*8 + t + 4]);
            qa[ks][3] = tf32u(q8[ks*8 + t + 4]);
        }
    }

    float oacc[8][4];
    #pragma unroll
    for (int i = 0; i < 8; i++)
        #pragma unroll
        for (int j = 0; j < 4; j++) oacc[i][j] = 0.0f;
    float m0 = -1e30f, m1 = -1e30f, l0 = 0.0f, l1 = 0.0f;

    // tile loader (all 256 threads; 4 x 16B chunks of K and of V each)
    auto issue = [&](int jt, int buf) {
        const int j0 = jt * 64;
        float* Kd = Kb + buf * TILE_F;
        float* Vd = Vb + buf * TILE_F;
        #pragma unroll
        for (int u = 0; u < 4; u++) {
            int lin = u * 256 + tid;
            int r = lin >> 4, c4 = (lin & 15) * 4;
            const float *kp, *vp;
            if (MODE == 0) {
                if (j0 + r < XL_) {
                    const float* base = xl + (((long)(b * XL_ + j0 + r)) * 2) * HD_ + h * D_ + c4;
                    kp = base; vp = base + HD_;
                } else {
                    int s = j0 + r - XL_;
                    kp = knew + ((long)(b * S_ + s)) * HD_ + h * D_ + c4;
                    vp = vnew + ((long)(b * S_ + s)) * HD_ + h * D_ + c4;
                }
            } else {
                const float* base = kve + ((long)b * ST_ + j0 + r) * (2 * HD_) + h * D_ + c4;
                kp = base; vp = base + HD_;
            }
            cpasync16(smaddr(Kd + r * PADW + c4), kp);
            cpasync16(smaddr(Vd + r * PADW + c4), vp);
        }
        asm volatile("cp.async.commit_group;" ::: "memory");
    };

    issue(0, 0);
    issue(1, 1);

    for (int jt = 0; jt < ntiles; jt++) {
        const int cur = jt & 1;
        const int j0 = jt * 64;
        if (jt + 1 < ntiles) asm volatile("cp.async.wait_group 1;" ::: "memory");
        else                 asm volatile("cp.async.wait_group 0;" ::: "memory");
        __syncthreads();

        const float* Kc = Kb + cur * TILE_F;
        const float* Vc = Vb + cur * TILE_F;

        // S = Q @ K^T
        float sacc[8][4];
        #pragma unroll
        for (int i = 0; i < 8; i++)
            #pragma unroll
            for (int j = 0; j < 4; j++) sacc[i][j] = 0.0f;
        #pragma unroll
        for (int ks = 0; ks < 8; ks++) {
            #pragma unroll
            for (int nf = 0; nf < 8; nf++) {
                unsigned b0 = __float_as_uint(Kc[(nf*8 + g) * PADW + ks*8 + t]);
                unsigned b1 = __float_as_uint(Kc[(nf*8 + g) * PADW + ks*8 + t + 4]);
                mma8(sacc[nf], qa[ks], b0, b1);
            }
        }

        // logits
        float mx0 = -1e30f, mx1 = -1e30f;
        const bool maskt = (MODE == 0) && (jt >= ntiles - 2);
        #pragma unroll
        for (int nf = 0; nf < 8; nf++) {
            int jc = nf * 8 + 2 * t;
            float vx, vy, vz, vw;
            if (MODE == 0) {
                const float* r0p = rel + (((long)h * S_ + i0 + wr + g) * J_) + j0 + jc;
                const float* r1p = r0p + 8 * J_;
                float2 ra = *(const float2*)r0p;
                float2 rb = *(const float2*)r1p;
                vx = (sacc[nf][0] + ra.x) * 0.125f;
                vy = (sacc[nf][1] + ra.y) * 0.125f;
                vz = (sacc[nf][2] + rb.x) * 0.125f;
                vw = (sacc[nf][3] + rb.y) * 0.125f;
                if (maskt) {
                    int thr = j0 + jc - XL_ - i0;     // global col offset vs row base
                    int ir0 = wr + g, ir1 = ir0 + 8;
                    if (thr     > ir0) vx = -1e30f;
                    if (thr + 1 > ir0) vy = -1e30f;
                    if (thr     > ir1) vz = -1e30f;
                    if (thr + 1 > ir1) vw = -1e30f;
                }
            } else {
                vx = sacc[nf][0] * 0.125f;
                vy = sacc[nf][1] * 0.125f;
                vz = sacc[nf][2] * 0.125f;
                vw = sacc[nf][3] * 0.125f;
            }
            sacc[nf][0] = vx; sacc[nf][1] = vy; sacc[nf][2] = vz; sacc[nf][3] = vw;
            mx0 = fmaxf(mx0, fmaxf(vx, vy));
            mx1 = fmaxf(mx1, fmaxf(vz, vw));
        }
        mx0 = fmaxf(mx0, __shfl_xor_sync(0xffffffffu, mx0, 1));
        mx0 = fmaxf(mx0, __shfl_xor_sync(0xffffffffu, mx0, 2));
        mx1 = fmaxf(mx1, __shfl_xor_sync(0xffffffffu, mx1, 1));
        mx1 = fmaxf(mx1, __shfl_xor_sync(0xffffffffu, mx1, 2));
        const float mn0 = fmaxf(m0, mx0), mn1 = fmaxf(m1, mx1);
        const float a0 = __expf(m0 - mn0), a1 = __expf(m1 - mn1);
        m0 = mn0; m1 = mn1;
        float s0 = 0.0f, s1 = 0.0f;
        #pragma unroll
        for (int nf = 0; nf < 8; nf++) {
            float px = __expf(sacc[nf][0] - mn0), py = __expf(sacc[nf][1] - mn0);
            float pz = __expf(sacc[nf][2] - mn1), pw = __expf(sacc[nf][3] - mn1);
            s0 += px + py; s1 += pz + pw;
            sacc[nf][0] = px; sacc[nf][1] = py; sacc[nf][2] = pz; sacc[nf][3] = pw;
            oacc[nf][0] *= a0; oacc[nf][1] *= a0;
            oacc[nf][2] *= a1; oacc[nf][3] *= a1;
        }
        s0 += __shfl_xor_sync(0xffffffffu, s0, 1);
        s0 += __shfl_xor_sync(0xffffffffu, s0, 2);
        s1 += __shfl_xor_sync(0xffffffffu, s1, 1);
        s1 += __shfl_xor_sync(0xffffffffu, s1, 2);
        l0 = l0 * a0 + s0;
        l1 = l1 * a1 + s1;

        // stage P (warp-local rows)
        #pragma unroll
        for (int nf = 0; nf < 8; nf++) {
            int jc = nf * 8 + 2 * t;
            Pb[(wr + g) * PADW + jc]         = tf32f(sacc[nf][0]);
            Pb[(wr + g) * PADW + jc + 1]     = tf32f(sacc[nf][1]);
            Pb[(wr + g + 8) * PADW + jc]     = tf32f(sacc[nf][2]);
            Pb[(wr + g + 8) * PADW + jc + 1] = tf32f(sacc[nf][3]);
        }
        __syncwarp();
        // O += P @ V
        #pragma unroll
        for (int ks = 0; ks < 8; ks++) {
            unsigned pa[4];
            pa[0] = __float_as_uint(Pb[(wr + g) * PADW + ks*8 + t]);
            pa[1] = __float_as_uint(Pb[(wr + g + 8) * PADW + ks*8 + t]);
            pa[2] = __float_as_uint(Pb[(wr + g) * PADW + ks*8 + t + 4]);
            pa[3] = __float_as_uint(Pb[(wr + g + 8) * PADW + ks*8 + t + 4]);
            #pragma unroll
            for (int nf = 0; nf < 8; nf++) {
                unsigned b0 = __float_as_uint(Vc[(ks*8 + t) * PADW + nf*8 + g]);
                unsigned b1 = __float_as_uint(Vc[(ks*8 + t + 4) * PADW + nf*8 + g]);
                mma8(oacc[nf], pa, b0, b1);
            }
        }

        __syncthreads();                    // K/V[cur] fully consumed
        if (jt + 2 < ntiles) issue(jt + 2, cur);
    }

    // epilogue
    const float gv = gate[h];
    const float gg = 1.0f / (1.0f + __expf(-gv));
    const float f = (MODE == 0) ? gg : (1.0f - gg);
    const float inv0 = f / l0, inv1 = f / l1;
    float* dst = (MODE == 0) ? outMain : outExt;
    const long base0 = ((long)(b * S_ + i0 + wr + g)) * HD_ + h * D_;
    const long base8 = base0 + 8 * HD_;
    #pragma unroll
    for (int nf = 0; nf < 8; nf++) {
        int jc = nf * 8 + 2 * t;
        float2 r0v = { oacc[nf][0] * inv0, oacc[nf][1] * inv0 };
        float2 r1v = { oacc[nf][2] * inv1, oacc[nf][3] * inv1 };
        *(float2*)&dst[base0 + jc] = r0v;
        *(float2*)&dst[base8 + jc] = r1v;
    }
}

// ---------------------------------------------------------------------------
extern "C" void kernel_launch(void* const* d_in, const int* in_sizes, int n_in,
                              void* d_out, int out_size) {
    const float* input = (const float*)d_in[0];
    const float* rel   = (const float*)d_in[1];
    const float* xl    = (const float*)d_in[2];
    const float* kve   = (const float*)d_in[3];
    const float* Wq = (const float*)d_in[4];  const float* bq = (const float*)d_in[5];
    const float* Wk = (const float*)d_in[6];  const float* bk = (const float*)d_in[7];
    const float* Wv = (const float*)d_in[8];  const float* bv = (const float*)d_in[9];
    const float* Wo = (const float*)d_in[10]; const float* bo = (const float*)d_in[11];
    const float* gate = (const float*)d_in[12];

    float* out = (float*)d_out;                    // (B,S,E)
    float* out_kv = out + (long)B_ * S_ * E_;      // (B,S,2,HD)

    float *q, *k, *v, *fused, *ext;
    cudaGetSymbolAddress((void**)&q, g_q);
    cudaGetSymbolAddress((void**)&k, g_k);
    cudaGetSymbolAddress((void**)&v, g_v);
    cudaGetSymbolAddress((void**)&fused, g_fused);
    cudaGetSymbolAddress((void**)&ext, g_ext);

    cudaFuncSetAttribute(flash2, cudaFuncAttributeMaxDynamicSharedMemorySize, FLASH_SMEM);

    const dim3 t(256);

    // Fused Q/K/V projections (3xTF32)
    gemm3_qkv<<<dim3(24, 16), t>>>(input, Wq, Wk, Wv, bq, bk, bv, q, k, v);
    // L2 norm over full HD
    l2norm_rows<<<MROWS, t>>>(q);
    l2norm_rows<<<MROWS, t>>>(k);
    // current_kv output
    copy_kv<<<(B_ * S_ * HD_) / 256, t>>>(out_kv);

    // Flash attention: main (z=0) and external (z=1) in one launch
    flash2<<<dim3(S_ / 128, B_ * H_, 2), t, FLASH_SMEM>>>(q, xl, k, v, kve, rel, gate,
                                                          fused, ext);

    // Output projection: (fused + ext) @ Wo^T + bo
    gemm3_nt<<<dim3(E_ / 128, MROWS / 128), t>>>(fused, ext, Wo, bo, out, E_, HD_);
}

// round 5
// speedup vs baseline: 2.8958x; 1.1806x over previous
#include <cuda_runtime.h>
#include <math.h>
#include <float.h>

// Problem constants
#define B_    4
#define S_    512
#define E_    1024
#define H_    16
#define D_    64
#define HD_   1024
#define XL_   512
#define J_    1024      // XL + S
#define TOPK_ 8
#define ST_   4096      // S * TOPK
#define MROWS 2048      // B * S

// Static scratch (no allocations allowed)
__device__ float g_q[B_*S_*HD_];
__device__ float g_k[B_*S_*HD_];
__device__ float g_v[B_*S_*HD_];
__device__ float g_fused[B_*S_*HD_];
__device__ float g_ext[B_*S_*HD_];

// ---------------------------------------------------------------------------
// Helpers
// ---------------------------------------------------------------------------
__device__ __forceinline__ unsigned tf32u(float x) {
    unsigned u;
    asm("cvt.rna.tf32.f32 %0, %1;" : "=r"(u) : "f"(x));
    return u;
}
__device__ __forceinline__ float tf32f(float x) { return __uint_as_float(tf32u(x)); }

__device__ __forceinline__ void mma8(float* c, const unsigned* a, unsigned b0, unsigned b1) {
    asm volatile(
        "mma.sync.aligned.m16n8k8.row.col.f32.tf32.tf32.f32 "
        "{%0,%1,%2,%3},{%4,%5,%6,%7},{%8,%9},{%0,%1,%2,%3};"
        : "+f"(c[0]), "+f"(c[1]), "+f"(c[2]), "+f"(c[3])
        : "r"(a[0]), "r"(a[1]), "r"(a[2]), "r"(a[3]), "r"(b0), "r"(b1));
}

__device__ __forceinline__ unsigned smaddr(const void* p) {
    return (unsigned)__cvta_generic_to_shared(p);
}
__device__ __forceinline__ void cpasync16(unsigned s, const void* g) {
    asm volatile("cp.async.cg.shared.global [%0], [%1], 16;" :: "r"(s), "l"(g));
}
#define CP_COMMIT() asm volatile("cp.async.commit_group;" ::: "memory")
#define CP_WAIT(n)  asm volatile("cp.async.wait_group %0;" :: "n"(n) : "memory")

__device__ __forceinline__ float4 f4add(float4 a, float4 b) {
    return make_float4(a.x + b.x, a.y + b.y, a.z + b.z, a.w + b.w);
}

__device__ __forceinline__ float blockSum256(float v) {
    __shared__ float sh[8];
    #pragma unroll
    for (int o = 16; o > 0; o >>= 1) v += __shfl_xor_sync(0xffffffffu, v, o);
    if ((threadIdx.x & 31) == 0) sh[threadIdx.x >> 5] = v;
    __syncthreads();
    if (threadIdx.x < 32) {
        float w = (threadIdx.x < 8) ? sh[threadIdx.x] : 0.0f;
        #pragma unroll
        for (int o = 4; o > 0; o >>= 1) w += __shfl_xor_sync(0xffffffffu, w, o);
        if (threadIdx.x == 0) sh[0] = w;
    }
    __syncthreads();
    float r = sh[0];
    __syncthreads();
    return r;
}

// ---------------------------------------------------------------------------
// QKV projection, 3xTF32, cp.async double-buffered raw tiles, split-at-load.
// Tile 128x128x16, 256 threads. smem layout: [row][KSTR] row-major.
// ---------------------------------------------------------------------------
#define KSTR 20
__global__ void __launch_bounds__(256) gemm3_qkv(
    const float* __restrict__ A,
    const float* __restrict__ Wq, const float* __restrict__ Wk, const float* __restrict__ Wv,
    const float* __restrict__ bq, const float* __restrict__ bk, const float* __restrict__ bv,
    float* __restrict__ qo, float* __restrict__ ko, float* __restrict__ vo)
{
    __shared__ float As[2][128 * KSTR];
    __shared__ float Bs[2][128 * KSTR];

    const int which = blockIdx.x >> 3;
    const int bn = (blockIdx.x & 7) * 128;
    const int bm = blockIdx.y * 128;
    const float* W = (which == 0) ? Wq : (which == 1) ? Wk : Wv;
    const float* bias = (which == 0) ? bq : (which == 1) ? bk : bv;
    float* C = (which == 0) ? qo : (which == 1) ? ko : vo;

    const int tid = threadIdx.x;
    const int w = tid >> 5, lane = tid & 31;
    const int g = lane >> 2, t = lane & 3;
    const int wm = (w & 1) * 64, wn = (w >> 1) * 32;

    // cp.async assignment: 2 chunks of 16B each for A and B
    const int r = tid >> 1, cc = (tid & 1) * 8;
    const float* Ap = A + (long)(bm + r) * E_ + cc;
    const float* Wp = W + (long)(bn + r) * E_ + cc;

    auto issue = [&](int kc, int st) {
        const int k0 = kc * 16;
        cpasync16(smaddr(&As[st][r * KSTR + cc]),     Ap + k0);
        cpasync16(smaddr(&As[st][r * KSTR + cc + 4]), Ap + k0 + 4);
        cpasync16(smaddr(&Bs[st][r * KSTR + cc]),     Wp + k0);
        cpasync16(smaddr(&Bs[st][r * KSTR + cc + 4]), Wp + k0 + 4);
        CP_COMMIT();
    };

    float acc[4][4][4];
    #pragma unroll
    for (int mi = 0; mi < 4; mi++)
        #pragma unroll
        for (int ni = 0; ni < 4; ni++)
            #pragma unroll
            for (int x = 0; x < 4; x++) acc[mi][ni][x] = 0.0f;

    issue(0, 0);
    issue(1, 1);

    const int NKC = E_ / 16;   // 64
    for (int kc = 0; kc < NKC; kc++) {
        const int st = kc & 1;
        if (kc + 1 < NKC) CP_WAIT(1); else CP_WAIT(0);
        __syncthreads();
        const float* Ar = As[st];
        const float* Br = Bs[st];

        #pragma unroll
        for (int kk = 0; kk < 16; kk += 8) {
            unsigned ah[4][4], al[4][4], bh[4][2], bl[4][2];
            #pragma unroll
            for (int mi = 0; mi < 4; mi++) {
                const int mb = wm + mi * 16;
                float r0 = Ar[(mb + g) * KSTR + kk + t];
                float r1 = Ar[(mb + g + 8) * KSTR + kk + t];
                float r2 = Ar[(mb + g) * KSTR + kk + t + 4];
                float r3 = Ar[(mb + g + 8) * KSTR + kk + t + 4];
                float h0 = tf32f(r0), h1 = tf32f(r1), h2 = tf32f(r2), h3 = tf32f(r3);
                ah[mi][0] = __float_as_uint(h0); al[mi][0] = __float_as_uint(r0 - h0);
                ah[mi][1] = __float_as_uint(h1); al[mi][1] = __float_as_uint(r1 - h1);
                ah[mi][2] = __float_as_uint(h2); al[mi][2] = __float_as_uint(r2 - h2);
                ah[mi][3] = __float_as_uint(h3); al[mi][3] = __float_as_uint(r3 - h3);
            }
            #pragma unroll
            for (int ni = 0; ni < 4; ni++) {
                const int nb = wn + ni * 8;
                float s0 = Br[(nb + g) * KSTR + kk + t];
                float s1 = Br[(nb + g) * KSTR + kk + t + 4];
                float h0 = tf32f(s0), h1 = tf32f(s1);
                bh[ni][0] = __float_as_uint(h0); bl[ni][0] = __float_as_uint(s0 - h0);
                bh[ni][1] = __float_as_uint(h1); bl[ni][1] = __float_as_uint(s1 - h1);
            }
            #pragma unroll
            for (int mi = 0; mi < 4; mi++)
                #pragma unroll
                for (int ni = 0; ni < 4; ni++) {
                    mma8(acc[mi][ni], ah[mi], bh[ni][0], bh[ni][1]);
                    mma8(acc[mi][ni], ah[mi], bl[ni][0], bl[ni][1]);
                    mma8(acc[mi][ni], al[mi], bh[ni][0], bh[ni][1]);
                }
        }
        __syncthreads();
        if (kc + 2 < NKC) issue(kc + 2, st);
    }

    #pragma unroll
    for (int mi = 0; mi < 4; mi++) {
        const int r0 = bm + wm + mi * 16 + g;
        #pragma unroll
        for (int ni = 0; ni < 4; ni++) {
            const int col = bn + wn + ni * 8 + 2 * t;
            const float bx = bias[col], by = bias[col + 1];
            float2 v0 = { acc[mi][ni][0] + bx, acc[mi][ni][1] + by };
            float2 v1 = { acc[mi][ni][2] + bx, acc[mi][ni][3] + by };
            *(float2*)&C[(long)r0 * HD_ + col] = v0;
            *(float2*)&C[(long)(r0 + 8) * HD_ + col] = v1;
        }
    }
}

// ---------------------------------------------------------------------------
// Output projection: C = (A + A2) @ W^T + bias (register-prefetch gemm3)
// ---------------------------------------------------------------------------
#define GSTR 136
__global__ void __launch_bounds__(256) gemm3_out(
    const float* __restrict__ A, const float* __restrict__ A2,
    const float* __restrict__ W, const float* __restrict__ bias,
    float* __restrict__ C)
{
    __shared__ float Ah[16][GSTR], Al[16][GSTR], Bh[16][GSTR], Bl[16][GSTR];
    const int tid = threadIdx.x;
    const int bm = blockIdx.y * 128, bn = blockIdx.x * 128;
    const int w = tid >> 5, lane = tid & 31;
    const int g = lane >> 2, t = lane & 3;
    const int wm = (w & 1) * 64, wn = (w >> 1) * 32;
    const int K = HD_, N = E_;

    const int r = tid >> 1, c0 = (tid & 1) * 8;
    const float* Ap = A + (long)(bm + r) * K + c0;
    const float* A2p = A2 + (long)(bm + r) * K + c0;
    const float* Wp = W + (long)(bn + r) * K + c0;

    float acc[4][4][4];
    #pragma unroll
    for (int mi = 0; mi < 4; mi++)
        #pragma unroll
        for (int ni = 0; ni < 4; ni++)
            #pragma unroll
            for (int x = 0; x < 4; x++) acc[mi][ni][x] = 0.0f;

    float4 pa0 = f4add(*(const float4*)(Ap), *(const float4*)(A2p));
    float4 pa1 = f4add(*(const float4*)(Ap + 4), *(const float4*)(A2p + 4));
    float4 pb0 = *(const float4*)(Wp), pb1 = *(const float4*)(Wp + 4);

    for (int k0 = 0; k0 < K; k0 += 16) {
        float4 na0, na1, nb0, nb1;
        if (k0 + 16 < K) {
            na0 = f4add(*(const float4*)(Ap + k0 + 16), *(const float4*)(A2p + k0 + 16));
            na1 = f4add(*(const float4*)(Ap + k0 + 20), *(const float4*)(A2p + k0 + 20));
            nb0 = *(const float4*)(Wp + k0 + 16); nb1 = *(const float4*)(Wp + k0 + 20);
        }
        __syncthreads();
        {
            const float av[8] = {pa0.x,pa0.y,pa0.z,pa0.w,pa1.x,pa1.y,pa1.z,pa1.w};
            const float bv[8] = {pb0.x,pb0.y,pb0.z,pb0.w,pb1.x,pb1.y,pb1.z,pb1.w};
            #pragma unroll
            for (int j = 0; j < 8; j++) {
                float ahv = tf32f(av[j]);
                float bhv = tf32f(bv[j]);
                Ah[c0 + j][r] = ahv; Al[c0 + j][r] = av[j] - ahv;
                Bh[c0 + j][r] = bhv; Bl[c0 + j][r] = bv[j] - bhv;
            }
        }
        __syncthreads();

        #pragma unroll
        for (int kk = 0; kk < 16; kk += 8) {
            unsigned ah[4][4], al[4][4], bh[4][2], bl[4][2];
            #pragma unroll
            for (int mi = 0; mi < 4; mi++) {
                const int mb = wm + mi * 16;
                ah[mi][0] = __float_as_uint(Ah[kk + t][mb + g]);
                ah[mi][1] = __float_as_uint(Ah[kk + t][mb + g + 8]);
                ah[mi][2] = __float_as_uint(Ah[kk + t + 4][mb + g]);
                ah[mi][3] = __float_as_uint(Ah[kk + t + 4][mb + g + 8]);
                al[mi][0] = __float_as_uint(Al[kk + t][mb + g]);
                al[mi][1] = __float_as_uint(Al[kk + t][mb + g + 8]);
                al[mi][2] = __float_as_uint(Al[kk + t + 4][mb + g]);
                al[mi][3] = __float_as_uint(Al[kk + t + 4][mb + g + 8]);
            }
            #pragma unroll
            for (int ni = 0; ni < 4; ni++) {
                const int nb = wn + ni * 8;
                bh[ni][0] = __float_as_uint(Bh[kk + t][nb + g]);
                bh[ni][1] = __float_as_uint(Bh[kk + t + 4][nb + g]);
                bl[ni][0] = __float_as_uint(Bl[kk + t][nb + g]);
                bl[ni][1] = __float_as_uint(Bl[kk + t + 4][nb + g]);
            }
            #pragma unroll
            for (int mi = 0; mi < 4; mi++)
                #pragma unroll
                for (int ni = 0; ni < 4; ni++) {
                    mma8(acc[mi][ni], ah[mi], bh[ni][0], bh[ni][1]);
                    mma8(acc[mi][ni], ah[mi], bl[ni][0], bl[ni][1]);
                    mma8(acc[mi][ni], al[mi], bh[ni][0], bh[ni][1]);
                }
        }
        pa0 = na0; pa1 = na1; pb0 = nb0; pb1 = nb1;
    }

    #pragma unroll
    for (int mi = 0; mi < 4; mi++) {
        const int r0 = bm + wm + mi * 16 + g;
        #pragma unroll
        for (int ni = 0; ni < 4; ni++) {
            const int col = bn + wn + ni * 8 + 2 * t;
            const float bx = bias[col], by = bias[col + 1];
            float2 v0 = { acc[mi][ni][0] + bx, acc[mi][ni][1] + by };
            float2 v1 = { acc[mi][ni][2] + bx, acc[mi][ni][3] + by };
            *(float2*)&C[(long)r0 * N + col] = v0;
            *(float2*)&C[(long)(r0 + 8) * N + col] = v1;
        }
    }
}

// ---------------------------------------------------------------------------
// L2-normalize rows of q (first MROWS blocks) and k (next MROWS blocks)
// ---------------------------------------------------------------------------
__global__ void l2norm_qk(float* __restrict__ q, float* __restrict__ k) {
    float* x = (blockIdx.x < MROWS) ? q : k;
    const long base = (long)(blockIdx.x & (MROWS - 1)) * HD_;
    float ss = 0.0f;
    for (int c = threadIdx.x; c < HD_; c += 256) { float v = x[base + c]; ss += v * v; }
    ss = blockSum256(ss);
    const float inv = 1.0f / fmaxf(sqrtf(ss), 1e-12f);
    for (int c = threadIdx.x; c < HD_; c += 256) x[base + c] *= inv;
}

__global__ void copy_kv(float* __restrict__ out_kv) {
    const long idx = (long)blockIdx.x * 256 + threadIdx.x;
    const int c = (int)(idx % HD_);
    const long r = idx / HD_;
    out_kv[(r * 2) * HD_ + c]     = g_k[idx];
    out_kv[(r * 2 + 1) * HD_ + c] = g_v[idx];
}

// ---------------------------------------------------------------------------
// Flash v3: 64-row q tiles, 128 threads (4 warps x 16 rows),
// cp.async double-buffered K/V, dedicated P buffer. 87KB smem -> 2 CTAs/SM.
// blockIdx.z = 0: main (causal + rel_pos) -> outMain = g * qkv
// blockIdx.z = 1: external kNN            -> outExt  = (1-g) * qkv_ext
// ---------------------------------------------------------------------------
#define PADW 68
#define TILE_F (64 * PADW)
#define FLASH_SMEM (5 * TILE_F * 4)   // 87040 bytes

__global__ void __launch_bounds__(128) flash3(
    const float* __restrict__ q, const float* __restrict__ xl,
    const float* __restrict__ knew, const float* __restrict__ vnew,
    const float* __restrict__ kve, const float* __restrict__ rel,
    const float* __restrict__ gate,
    float* __restrict__ outMain, float* __restrict__ outExt)
{
    extern __shared__ float smf[];
    float* Kb = smf;                     // 2 x [64][PADW]
    float* Vb = smf + 2 * TILE_F;        // 2 x [64][PADW]
    float* Pb = smf + 4 * TILE_F;        // [64][PADW]

    const int MODE = blockIdx.z;
    const int qt = blockIdx.x, z = blockIdx.y;
    const int b = z >> 4, h = z & 15;
    const int i0 = qt * 64;
    const int tid = threadIdx.x;
    const int w = tid >> 5, lane = tid & 31;
    const int g = lane >> 2, t = lane & 3;
    const int wr = w * 16;

    const int ntiles = (MODE == 0) ? (9 + qt) : 64;

    // Q fragments (resident, tf32)
    unsigned qa[8][4];
    {
        const float* q0 = q + ((long)(b * S_ + i0 + wr + g)) * HD_ + h * D_;
        const float* q8 = q0 + 8 * HD_;
        #pragma unroll
        for (int ks = 0; ks < 8; ks++) {
            qa[ks][0] = tf32u(q0[ks*8 + t]);
            qa[ks][1] = tf32u(q8[ks*8 + t]);
            qa[ks][2] = tf32u(q0[ks*8 + t + 4]);
            qa[ks][3] = tf32u(q8[ks*8 + t + 4]);
        }
    }

    float oacc[8][4];
    #pragma unroll
    for (int i = 0; i < 8; i++)
        #pragma unroll
        for (int j = 0; j < 4; j++) oacc[i][j] = 0.0f;
    float m0 = -1e30f, m1 = -1e30f, l0 = 0.0f, l1 = 0.0f;

    // tile loader: 128 threads x 8 chunks of K and of V
    auto issue = [&](int jt, int buf) {
        const int j0 = jt * 64;
        float* Kd = Kb + buf * TILE_F;
        float* Vd = Vb + buf * TILE_F;
        #pragma unroll
        for (int u = 0; u < 8; u++) {
            int lin = u * 128 + tid;
            int r = lin >> 4, c4 = (lin & 15) * 4;
            const float *kp, *vp;
            if (MODE == 0) {
                if (j0 + r < XL_) {
                    const float* base = xl + (((long)(b * XL_ + j0 + r)) * 2) * HD_ + h * D_ + c4;
                    kp = base; vp = base + HD_;
                } else {
                    int s = j0 + r - XL_;
                    kp = knew + ((long)(b * S_ + s)) * HD_ + h * D_ + c4;
                    vp = vnew + ((long)(b * S_ + s)) * HD_ + h * D_ + c4;
                }
            } else {
                const float* base = kve + ((long)b * ST_ + j0 + r) * (2 * HD_) + h * D_ + c4;
                kp = base; vp = base + HD_;
            }
            cpasync16(smaddr(Kd + r * PADW + c4), kp);
            cpasync16(smaddr(Vd + r * PADW + c4), vp);
        }
        CP_COMMIT();
    };

    issue(0, 0);
    issue(1, 1);

    for (int jt = 0; jt < ntiles; jt++) {
        const int cur = jt & 1;
        const int j0 = jt * 64;
        if (jt + 1 < ntiles) CP_WAIT(1); else CP_WAIT(0);
        __syncthreads();

        const float* Kc = Kb + cur * TILE_F;
        const float* Vc = Vb + cur * TILE_F;

        // S = Q @ K^T (warp: 16 rows x 64 cols)
        float sacc[8][4];
        #pragma unroll
        for (int i = 0; i < 8; i++)
            #pragma unroll
            for (int j = 0; j < 4; j++) sacc[i][j] = 0.0f;
        #pragma unroll
        for (int ks = 0; ks < 8; ks++) {
            #pragma unroll
            for (int nf = 0; nf < 8; nf++) {
                unsigned b0 = __float_as_uint(Kc[(nf*8 + g) * PADW + ks*8 + t]);
                unsigned b1 = __float_as_uint(Kc[(nf*8 + g) * PADW + ks*8 + t + 4]);
                mma8(sacc[nf], qa[ks], b0, b1);
            }
        }

        // logits
        float mx0 = -1e30f, mx1 = -1e30f;
        const bool maskt = (MODE == 0) && (jt == ntiles - 1);
        #pragma unroll
        for (int nf = 0; nf < 8; nf++) {
            int jc = nf * 8 + 2 * t;
            float vx, vy, vz, vw;
            if (MODE == 0) {
                const float* r0p = rel + (((long)h * S_ + i0 + wr + g) * J_) + j0 + jc;
                const float* r1p = r0p + 8 * J_;
                float2 ra = *(const float2*)r0p;
                float2 rb = *(const float2*)r1p;
                vx = (sacc[nf][0] + ra.x) * 0.125f;
                vy = (sacc[nf][1] + ra.y) * 0.125f;
                vz = (sacc[nf][2] + rb.x) * 0.125f;
                vw = (sacc[nf][3] + rb.y) * 0.125f;
                if (maskt) {
                    int thr = j0 + jc - XL_ - i0;
                    int ir0 = wr + g, ir1 = ir0 + 8;
                    if (thr     > ir0) vx = -1e30f;
                    if (thr + 1 > ir0) vy = -1e30f;
                    if (thr     > ir1) vz = -1e30f;
                    if (thr + 1 > ir1) vw = -1e30f;
                }
            } else {
                vx = sacc[nf][0] * 0.125f;
                vy = sacc[nf][1] * 0.125f;
                vz = sacc[nf][2] * 0.125f;
                vw = sacc[nf][3] * 0.125f;
            }
            sacc[nf][0] = vx; sacc[nf][1] = vy; sacc[nf][2] = vz; sacc[nf][3] = vw;
            mx0 = fmaxf(mx0, fmaxf(vx, vy));
            mx1 = fmaxf(mx1, fmaxf(vz, vw));
        }
        mx0 = fmaxf(mx0, __shfl_xor_sync(0xffffffffu, mx0, 1));
        mx0 = fmaxf(mx0, __shfl_xor_sync(0xffffffffu, mx0, 2));
        mx1 = fmaxf(mx1, __shfl_xor_sync(0xffffffffu, mx1, 1));
        mx1 = fmaxf(mx1, __shfl_xor_sync(0xffffffffu, mx1, 2));
        const float mn0 = fmaxf(m0, mx0), mn1 = fmaxf(m1, mx1);
        const float a0 = __expf(m0 - mn0), a1 = __expf(m1 - mn1);
        m0 = mn0; m1 = mn1;
        float s0 = 0.0f, s1 = 0.0f;
        #pragma unroll
        for (int nf = 0; nf < 8; nf++) {
            float px = __expf(sacc[nf][0] - mn0), py = __expf(sacc[nf][1] - mn0);
            float pz = __expf(sacc[nf][2] - mn1), pw = __expf(sacc[nf][3] - mn1);
            s0 += px + py; s1 += pz + pw;
            sacc[nf][0] = px; sacc[nf][1] = py; sacc[nf][2] = pz; sacc[nf][3] = pw;
            oacc[nf][0] *= a0; oacc[nf][1] *= a0;
            oacc[nf][2] *= a1; oacc[nf][3] *= a1;
        }
        s0 += __shfl_xor_sync(0xffffffffu, s0, 1);
        s0 += __shfl_xor_sync(0xffffffffu, s0, 2);
        s1 += __shfl_xor_sync(0xffffffffu, s1, 1);
        s1 += __shfl_xor_sync(0xffffffffu, s1, 2);
        l0 = l0 * a0 + s0;
        l1 = l1 * a1 + s1;

        // stage P (warp-owned 16 rows)
        #pragma unroll
        for (int nf = 0; nf < 8; nf++) {
            int jc = nf * 8 + 2 * t;
            Pb[(wr + g) * PADW + jc]         = tf32f(sacc[nf][0]);
            Pb[(wr + g) * PADW + jc + 1]     = tf32f(sacc[nf][1]);
            Pb[(wr + g + 8) * PADW + jc]     = tf32f(sacc[nf][2]);
            Pb[(wr + g + 8) * PADW + jc + 1] = tf32f(sacc[nf][3]);
        }
        __syncwarp();
        // O += P @ V
        #pragma unroll
        for (int ks = 0; ks < 8; ks++) {
            unsigned pa[4];
            pa[0] = __float_as_uint(Pb[(wr + g) * PADW + ks*8 + t]);
            pa[1] = __float_as_uint(Pb[(wr + g + 8) * PADW + ks*8 + t]);
            pa[2] = __float_as_uint(Pb[(wr + g) * PADW + ks*8 + t + 4]);
            pa[3] = __float_as_uint(Pb[(wr + g + 8) * PADW + ks*8 + t + 4]);
            #pragma unroll
            for (int nf = 0; nf < 8; nf++) {
                unsigned b0 = __float_as_uint(Vc[(ks*8 + t) * PADW + nf*8 + g]);
                unsigned b1 = __float_as_uint(Vc[(ks*8 + t + 4) * PADW + nf*8 + g]);
                mma8(oacc[nf], pa, b0, b1);
            }
        }

        __syncthreads();   // K/V[cur] fully consumed
        if (jt + 2 < ntiles) issue(jt + 2, cur);
    }

    // epilogue
    const float gv = gate[h];
    const float gg = 1.0f / (1.0f + __expf(-gv));
    const float f = (MODE == 0) ? gg : (1.0f - gg);
    const float inv0 = f / l0, inv1 = f / l1;
    float* dst = (MODE == 0) ? outMain : outExt;
    const long base0 = ((long)(b * S_ + i0 + wr + g)) * HD_ + h * D_;
    const long base8 = base0 + 8 * HD_;
    #pragma unroll
    for (int nf = 0; nf < 8; nf++) {
        int jc = nf * 8 + 2 * t;
        float2 r0v = { oacc[nf][0] * inv0, oacc[nf][1] * inv0 };
        float2 r1v = { oacc[nf][2] * inv1, oacc[nf][3] * inv1 };
        *(float2*)&dst[base0 + jc] = r0v;
        *(float2*)&dst[base8 + jc] = r1v;
    }
}

// ---------------------------------------------------------------------------
extern "C" void kernel_launch(void* const* d_in, const int* in_sizes, int n_in,
                              void* d_out, int out_size) {
    const float* input = (const float*)d_in[0];
    const float* rel   = (const float*)d_in[1];
    const float* xl    = (const float*)d_in[2];
    const float* kve   = (const float*)d_in[3];
    const float* Wq = (const float*)d_in[4];  const float* bq = (const float*)d_in[5];
    const float* Wk = (const float*)d_in[6];  const float* bk = (const float*)d_in[7];
    const float* Wv = (const float*)d_in[8];  const float* bv = (const float*)d_in[9];
    const float* Wo = (const float*)d_in[10]; const float* bo = (const float*)d_in[11];
    const float* gate = (const float*)d_in[12];

    float* out = (float*)d_out;                    // (B,S,E)
    float* out_kv = out + (long)B_ * S_ * E_;      // (B,S,2,HD)

    float *q, *k, *v, *fused, *ext;
    cudaGetSymbolAddress((void**)&q, g_q);
    cudaGetSymbolAddress((void**)&k, g_k);
    cudaGetSymbolAddress((void**)&v, g_v);
    cudaGetSymbolAddress((void**)&fused, g_fused);
    cudaGetSymbolAddress((void**)&ext, g_ext);

    cudaFuncSetAttribute(flash3, cudaFuncAttributeMaxDynamicSharedMemorySize, FLASH_SMEM);

    const dim3 t(256);

    // Fused Q/K/V projections (3xTF32, cp.async pipelined)
    gemm3_qkv<<<dim3(24, 16), t>>>(input, Wq, Wk, Wv, bq, bk, bv, q, k, v);
    // L2 norm of q and k over full HD
    l2norm_qk<<<2 * MROWS, t>>>(q, k);
    // current_kv output
    copy_kv<<<(B_ * S_ * HD_) / 256, t>>>(out_kv);

    // Flash attention: main (z=0) and external (z=1)
    flash3<<<dim3(S_ / 64, B_ * H_, 2), dim3(128), FLASH_SMEM>>>(q, xl, k, v, kve, rel, gate,
                                                                 fused, ext);

    // Output projection: (fused + ext) @ Wo^T + bo
    gemm3_out<<<dim3(E_ / 128, MROWS / 128), t>>>(fused, ext, Wo, bo, out);
}